// round 7
// baseline (speedup 1.0000x reference)
#include <cuda_runtime.h>
#include <math.h>

#define NNB  16
#define NOB  8
#define SDIM 4
#define H1   64
#define ED   16
#define HP   64
#define XC   85      // 1 + 4 + 64 + 16
#define BMAX 131072

typedef unsigned long long u64;

// SoA scratch: xT[f][b], stride BMAX
__device__ float g_xT[XC * BMAX];

// ---------------- transpose kernel: x[B][85] -> g_xT[85][BMAX] ----------------
__global__ void __launch_bounds__(256)
transpose_kernel(const float* __restrict__ x, int nb)
{
    __shared__ float tile[32][33];
    const int bBase = blockIdx.x * 32;
    const int fBase = blockIdx.y * 32;
    const int tx = threadIdx.x & 31;
    const int ty = threadIdx.x >> 5;

    #pragma unroll
    for (int r = ty; r < 32; r += 8) {
        const int b = bBase + r, f = fBase + tx;
        if (b < nb && f < XC)
            tile[r][tx] = x[(size_t)b * XC + f];
    }
    __syncthreads();
    #pragma unroll
    for (int r = ty; r < 32; r += 8) {
        const int f = fBase + r, b = bBase + tx;
        if (b < nb && f < XC)
            g_xT[(size_t)f * BMAX + b] = tile[tx][r];
    }
}

// ---------------- packed f32x2 helpers ----------------
__device__ __forceinline__ u64 dup2(float v) {
    u64 r; unsigned u = __float_as_uint(v);
    asm("mov.b64 %0, {%1, %1};" : "=l"(r) : "r"(u));
    return r;
}
__device__ __forceinline__ void unpack2(u64 v, float& a, float& b) {
    unsigned x, y;
    asm("mov.b64 {%0, %1}, %2;" : "=r"(x), "=r"(y) : "l"(v));
    a = __uint_as_float(x); b = __uint_as_float(y);
}
__device__ __forceinline__ u64 fma2(u64 a, u64 b, u64 c) {
    u64 d;
    asm("fma.rn.f32x2 %0, %1, %2, %3;" : "=l"(d) : "l"(a), "l"(b), "l"(c));
    return d;
}

__device__ __forceinline__ void barrier_acc(float e0, float e1, float D,
                                            float& bx, float& by) {
    const float px = -e0, py = -e1;
    const float q  = fmaf(px, px, py * py);
    const float rq = rsqrtf(q);
    const float nrm = q * rq;
    const float s  = 0.05f * __fdividef(1.0f, nrm * (nrm - D));
    bx = fmaf(s, px, bx);
    by = fmaf(s, py, by);
}

__global__ void __launch_bounds__(256, 2)
bnet_kernel(const float* __restrict__ Wp1n, const float* __restrict__ bp1n,
            const float* __restrict__ Wp2n, const float* __restrict__ bp2n,
            const float* __restrict__ Wr1n, const float* __restrict__ br1n,
            const float* __restrict__ Wr2n, const float* __restrict__ br2n,
            const float* __restrict__ Wp1o, const float* __restrict__ bp1o,
            const float* __restrict__ Wp2o, const float* __restrict__ bp2o,
            const float* __restrict__ Wr1o, const float* __restrict__ br1o,
            const float* __restrict__ Wr2o, const float* __restrict__ br2o,
            const float* __restrict__ Wpsi1, const float* __restrict__ bpsi1,
            const float* __restrict__ Wpsi2, const float* __restrict__ bpsi2,
            float* __restrict__ out, int nb)
{
    // phi-n weights as h-pairs: [p][k][2], p=h/2  (pair components adjacent)
    __shared__ __align__(16) float sWp1n_p[32 * 4 * 2];
    __shared__ __align__(16) float sbp1n[H1];
    __shared__ __align__(16) float sWp2n[H1 * ED];
    __shared__ __align__(16) float sbp2n[ED];        // pre-scaled by NNB
    __shared__ __align__(16) float sWr1n[ED * H1];
    __shared__ __align__(16) float sbr1n[H1];
    __shared__ __align__(16) float sWr2n[H1 * ED];
    __shared__ __align__(16) float sbr2n[ED];
    __shared__ __align__(16) float sWp1o_p[32 * 2 * 2];  // [p][k][2]
    __shared__ __align__(16) float sbp1o[H1];
    __shared__ __align__(16) float sWp2o[H1 * ED];
    __shared__ __align__(16) float sbp2o[ED];        // pre-scaled by NOB
    __shared__ __align__(16) float sWr1o[ED * H1];
    __shared__ __align__(16) float sbr1o[H1];
    __shared__ __align__(16) float sWr2o[H1 * ED];
    __shared__ __align__(16) float sbr2o[ED];
    __shared__ __align__(16) float sWpsi1[(2 * ED + SDIM) * HP];
    __shared__ __align__(16) float sbpsi1[HP];
    __shared__ __align__(16) float sWpsi2[HP * 2];
    __shared__ __align__(16) float sbpsi2[2];

    // ---- staging ----
    for (int i = threadIdx.x; i < 32 * 4 * 2; i += 256) {   // [p][k][c] <- Wp1n[k][2p+c]
        int p = i >> 3, k = (i >> 1) & 3, c = i & 1;
        sWp1n_p[i] = Wp1n[k * H1 + 2 * p + c];
    }
    for (int i = threadIdx.x; i < 32 * 2 * 2; i += 256) {   // [p][k][c] <- Wp1o[k][2p+c]
        int p = i >> 2, k = (i >> 1) & 1, c = i & 1;
        sWp1o_p[i] = Wp1o[k * H1 + 2 * p + c];
    }
    for (int i = threadIdx.x; i < ED; i += 256) {
        sbp2n[i] = (float)NNB * bp2n[i];
        sbp2o[i] = (float)NOB * bp2o[i];
    }
    {
        float* dsts[16]       = { sbp1n, sWp2n, sWr1n, sbr1n, sWr2n, sbr2n,
                                  sbp1o, sWp2o, sWr1o, sbr1o, sWr2o, sbr2o,
                                  sWpsi1, sbpsi1, sWpsi2, sbpsi2 };
        const float* srcs[16] = { bp1n, Wp2n, Wr1n, br1n, Wr2n, br2n,
                                  bp1o, Wp2o, Wr1o, br1o, Wr2o, br2o,
                                  Wpsi1, bpsi1, Wpsi2, bpsi2 };
        const int ns[16]      = { H1, H1*ED, ED*H1, H1, H1*ED, ED,
                                  H1, H1*ED, ED*H1, H1, H1*ED, ED,
                                  (2*ED+SDIM)*HP, HP, HP*2, 2 };
        for (int a = 0; a < 16; ++a)
            for (int i = threadIdx.x; i < ns[a]; i += 256)
                dsts[a][i] = srcs[a][i];
    }
    __syncthreads();

    const int t = blockIdx.x * blockDim.x + threadIdx.x;
    if (t >= nb) return;

    float bx = 0.f, by = 0.f;
    float sp[ED], rn[ED], ro[ED];

    // ======================= neighbor deep-set: phi =======================
    float hs[H1];
    #pragma unroll
    for (int h = 0; h < H1; ++h) hs[h] = 0.f;

    {
        const float* xb = g_xT + 5 * BMAX + t;   // neighbor features 5..68

        #pragma unroll 1
        for (int g = 0; g < 4; ++g) {
            const float* xg = xb + (size_t)(16 * g) * BMAX;
            u64 epk[16];
            #pragma unroll
            for (int k = 0; k < 4; ++k) {
                float e0 = xg[(size_t)(4 * k + 0) * BMAX];
                float e1 = xg[(size_t)(4 * k + 1) * BMAX];
                float e2 = xg[(size_t)(4 * k + 2) * BMAX];
                float e3 = xg[(size_t)(4 * k + 3) * BMAX];
                barrier_acc(e0, e1, 0.3f, bx, by);
                epk[4 * k + 0] = dup2(e0);
                epk[4 * k + 1] = dup2(e1);
                epk[4 * k + 2] = dup2(e2);
                epk[4 * k + 3] = dup2(e3);
            }

            #pragma unroll
            for (int p = 0; p < 32; ++p) {
                const u64 b2 = *reinterpret_cast<const u64*>(&sbp1n[2 * p]);
                const ulonglong2 wA = *reinterpret_cast<const ulonglong2*>(&sWp1n_p[p * 8]);
                const ulonglong2 wB = *reinterpret_cast<const ulonglong2*>(&sWp1n_p[p * 8 + 4]);
                #pragma unroll
                for (int ent = 0; ent < 4; ++ent) {
                    u64 v = b2;
                    v = fma2(epk[4 * ent + 0], wA.x, v);
                    v = fma2(epk[4 * ent + 1], wA.y, v);
                    v = fma2(epk[4 * ent + 2], wB.x, v);
                    v = fma2(epk[4 * ent + 3], wB.y, v);
                    float lo, hi; unpack2(v, lo, hi);
                    hs[2 * p]     += fmaxf(lo, 0.f);
                    hs[2 * p + 1] += fmaxf(hi, 0.f);
                }
            }
        }
    }
    // phi-n -> sp  (packed over o)
    {
        u64 sp2[8];
        #pragma unroll
        for (int j = 0; j < 8; ++j)
            sp2[j] = *reinterpret_cast<const u64*>(&sbp2n[2 * j]);
        #pragma unroll
        for (int h = 0; h < H1; ++h) {
            const u64 vv = dup2(hs[h]);
            const ulonglong2* wr = reinterpret_cast<const ulonglong2*>(&sWp2n[h * ED]);
            const ulonglong2 w0 = wr[0], w1 = wr[1], w2 = wr[2], w3 = wr[3];
            sp2[0] = fma2(vv, w0.x, sp2[0]); sp2[1] = fma2(vv, w0.y, sp2[1]);
            sp2[2] = fma2(vv, w1.x, sp2[2]); sp2[3] = fma2(vv, w1.y, sp2[3]);
            sp2[4] = fma2(vv, w2.x, sp2[4]); sp2[5] = fma2(vv, w2.y, sp2[5]);
            sp2[6] = fma2(vv, w3.x, sp2[6]); sp2[7] = fma2(vv, w3.y, sp2[7]);
        }
        #pragma unroll
        for (int j = 0; j < 8; ++j) unpack2(sp2[j], sp[2 * j], sp[2 * j + 1]);
    }
    // rho_n: relu(sp@Wr1n+br1n) @ Wr2n + br2n   (h-pairs, chunked 4x16)
    {
        u64 rn2[8];
        #pragma unroll
        for (int j = 0; j < 8; ++j)
            rn2[j] = *reinterpret_cast<const u64*>(&sbr2n[2 * j]);
        #pragma unroll 1
        for (int c = 0; c < 4; ++c) {
            const int base = c * 16;
            u64 hc2[8];
            #pragma unroll
            for (int q = 0; q < 8; ++q)
                hc2[q] = *reinterpret_cast<const u64*>(&sbr1n[base + 2 * q]);
            #pragma unroll
            for (int i = 0; i < ED; ++i) {
                const u64 vv = dup2(sp[i]);
                const ulonglong2* wr = reinterpret_cast<const ulonglong2*>(&sWr1n[i * H1 + base]);
                const ulonglong2 w0 = wr[0], w1 = wr[1], w2 = wr[2], w3 = wr[3];
                hc2[0] = fma2(vv, w0.x, hc2[0]); hc2[1] = fma2(vv, w0.y, hc2[1]);
                hc2[2] = fma2(vv, w1.x, hc2[2]); hc2[3] = fma2(vv, w1.y, hc2[3]);
                hc2[4] = fma2(vv, w2.x, hc2[4]); hc2[5] = fma2(vv, w2.y, hc2[5]);
                hc2[6] = fma2(vv, w3.x, hc2[6]); hc2[7] = fma2(vv, w3.y, hc2[7]);
            }
            #pragma unroll
            for (int q = 0; q < 8; ++q) {
                float u, v; unpack2(hc2[q], u, v);
                u = fmaxf(u, 0.f); v = fmaxf(v, 0.f);
                const u64 uu = dup2(u);
                const ulonglong2* wu = reinterpret_cast<const ulonglong2*>(&sWr2n[(base + 2 * q) * ED]);
                const ulonglong2 a0 = wu[0], a1 = wu[1], a2 = wu[2], a3 = wu[3];
                rn2[0] = fma2(uu, a0.x, rn2[0]); rn2[1] = fma2(uu, a0.y, rn2[1]);
                rn2[2] = fma2(uu, a1.x, rn2[2]); rn2[3] = fma2(uu, a1.y, rn2[3]);
                rn2[4] = fma2(uu, a2.x, rn2[4]); rn2[5] = fma2(uu, a2.y, rn2[5]);
                rn2[6] = fma2(uu, a3.x, rn2[6]); rn2[7] = fma2(uu, a3.y, rn2[7]);
                const u64 vv = dup2(v);
                const ulonglong2* wv = reinterpret_cast<const ulonglong2*>(&sWr2n[(base + 2 * q + 1) * ED]);
                const ulonglong2 b0 = wv[0], b1 = wv[1], b2 = wv[2], b3 = wv[3];
                rn2[0] = fma2(vv, b0.x, rn2[0]); rn2[1] = fma2(vv, b0.y, rn2[1]);
                rn2[2] = fma2(vv, b1.x, rn2[2]); rn2[3] = fma2(vv, b1.y, rn2[3]);
                rn2[4] = fma2(vv, b2.x, rn2[4]); rn2[5] = fma2(vv, b2.y, rn2[5]);
                rn2[6] = fma2(vv, b3.x, rn2[6]); rn2[7] = fma2(vv, b3.y, rn2[7]);
            }
        }
        #pragma unroll
        for (int j = 0; j < 8; ++j) unpack2(rn2[j], rn[2 * j], rn[2 * j + 1]);
    }

    // ======================= obstacle deep-set: phi =======================
    #pragma unroll
    for (int h = 0; h < H1; ++h) hs[h] = 0.f;
    {
        const float* xo = g_xT + 69 * BMAX + t;   // obstacle features 69..84
        u64 epk[16];
        #pragma unroll
        for (int k = 0; k < 8; ++k) {
            float e0 = xo[(size_t)(2 * k + 0) * BMAX];
            float e1 = xo[(size_t)(2 * k + 1) * BMAX];
            barrier_acc(e0, e1, 0.3f, bx, by);
            epk[2 * k + 0] = dup2(e0);
            epk[2 * k + 1] = dup2(e1);
        }
        #pragma unroll
        for (int p = 0; p < 32; ++p) {
            const u64 b2 = *reinterpret_cast<const u64*>(&sbp1o[2 * p]);
            const ulonglong2 w = *reinterpret_cast<const ulonglong2*>(&sWp1o_p[p * 4]);
            #pragma unroll
            for (int ent = 0; ent < 8; ++ent) {
                u64 v = b2;
                v = fma2(epk[2 * ent + 0], w.x, v);
                v = fma2(epk[2 * ent + 1], w.y, v);
                float lo, hi; unpack2(v, lo, hi);
                hs[2 * p]     += fmaxf(lo, 0.f);
                hs[2 * p + 1] += fmaxf(hi, 0.f);
            }
        }
    }
    // phi-o -> sp
    {
        u64 sp2[8];
        #pragma unroll
        for (int j = 0; j < 8; ++j)
            sp2[j] = *reinterpret_cast<const u64*>(&sbp2o[2 * j]);
        #pragma unroll
        for (int h = 0; h < H1; ++h) {
            const u64 vv = dup2(hs[h]);
            const ulonglong2* wr = reinterpret_cast<const ulonglong2*>(&sWp2o[h * ED]);
            const ulonglong2 w0 = wr[0], w1 = wr[1], w2 = wr[2], w3 = wr[3];
            sp2[0] = fma2(vv, w0.x, sp2[0]); sp2[1] = fma2(vv, w0.y, sp2[1]);
            sp2[2] = fma2(vv, w1.x, sp2[2]); sp2[3] = fma2(vv, w1.y, sp2[3]);
            sp2[4] = fma2(vv, w2.x, sp2[4]); sp2[5] = fma2(vv, w2.y, sp2[5]);
            sp2[6] = fma2(vv, w3.x, sp2[6]); sp2[7] = fma2(vv, w3.y, sp2[7]);
        }
        #pragma unroll
        for (int j = 0; j < 8; ++j) unpack2(sp2[j], sp[2 * j], sp[2 * j + 1]);
    }
    // rho_o
    {
        u64 ro2[8];
        #pragma unroll
        for (int j = 0; j < 8; ++j)
            ro2[j] = *reinterpret_cast<const u64*>(&sbr2o[2 * j]);
        #pragma unroll 1
        for (int c = 0; c < 4; ++c) {
            const int base = c * 16;
            u64 hc2[8];
            #pragma unroll
            for (int q = 0; q < 8; ++q)
                hc2[q] = *reinterpret_cast<const u64*>(&sbr1o[base + 2 * q]);
            #pragma unroll
            for (int i = 0; i < ED; ++i) {
                const u64 vv = dup2(sp[i]);
                const ulonglong2* wr = reinterpret_cast<const ulonglong2*>(&sWr1o[i * H1 + base]);
                const ulonglong2 w0 = wr[0], w1 = wr[1], w2 = wr[2], w3 = wr[3];
                hc2[0] = fma2(vv, w0.x, hc2[0]); hc2[1] = fma2(vv, w0.y, hc2[1]);
                hc2[2] = fma2(vv, w1.x, hc2[2]); hc2[3] = fma2(vv, w1.y, hc2[3]);
                hc2[4] = fma2(vv, w2.x, hc2[4]); hc2[5] = fma2(vv, w2.y, hc2[5]);
                hc2[6] = fma2(vv, w3.x, hc2[6]); hc2[7] = fma2(vv, w3.y, hc2[7]);
            }
            #pragma unroll
            for (int q = 0; q < 8; ++q) {
                float u, v; unpack2(hc2[q], u, v);
                u = fmaxf(u, 0.f); v = fmaxf(v, 0.f);
                const u64 uu = dup2(u);
                const ulonglong2* wu = reinterpret_cast<const ulonglong2*>(&sWr2o[(base + 2 * q) * ED]);
                const ulonglong2 a0 = wu[0], a1 = wu[1], a2 = wu[2], a3 = wu[3];
                ro2[0] = fma2(uu, a0.x, ro2[0]); ro2[1] = fma2(uu, a0.y, ro2[1]);
                ro2[2] = fma2(uu, a1.x, ro2[2]); ro2[3] = fma2(uu, a1.y, ro2[3]);
                ro2[4] = fma2(uu, a2.x, ro2[4]); ro2[5] = fma2(uu, a2.y, ro2[5]);
                ro2[6] = fma2(uu, a3.x, ro2[6]); ro2[7] = fma2(uu, a3.y, ro2[7]);
                const u64 vv = dup2(v);
                const ulonglong2* wv = reinterpret_cast<const ulonglong2*>(&sWr2o[(base + 2 * q + 1) * ED]);
                const ulonglong2 b0 = wv[0], b1 = wv[1], b2 = wv[2], b3 = wv[3];
                ro2[0] = fma2(vv, b0.x, ro2[0]); ro2[1] = fma2(vv, b0.y, ro2[1]);
                ro2[2] = fma2(vv, b1.x, ro2[2]); ro2[3] = fma2(vv, b1.y, ro2[3]);
                ro2[4] = fma2(vv, b2.x, ro2[4]); ro2[5] = fma2(vv, b2.y, ro2[5]);
                ro2[6] = fma2(vv, b3.x, ro2[6]); ro2[7] = fma2(vv, b3.y, ro2[7]);
            }
        }
        #pragma unroll
        for (int j = 0; j < 8; ++j) unpack2(ro2[j], ro[2 * j], ro[2 * j + 1]);
    }

    // ======================= psi head =======================
    const float g0 = g_xT[1 * BMAX + t], g1 = g_xT[2 * BMAX + t];
    const float g2 = g_xT[3 * BMAX + t], g3 = g_xT[4 * BMAX + t];
    u64 acc2 = *reinterpret_cast<const u64*>(&sbpsi2[0]);
    #pragma unroll 1
    for (int c = 0; c < 4; ++c) {
        const int base = c * 16;
        u64 hc2[8];
        #pragma unroll
        for (int q = 0; q < 8; ++q)
            hc2[q] = *reinterpret_cast<const u64*>(&sbpsi1[base + 2 * q]);
        #pragma unroll
        for (int i = 0; i < ED; ++i) {
            const u64 vv = dup2(rn[i]);
            const ulonglong2* wr = reinterpret_cast<const ulonglong2*>(&sWpsi1[i * HP + base]);
            const ulonglong2 w0 = wr[0], w1 = wr[1], w2 = wr[2], w3 = wr[3];
            hc2[0] = fma2(vv, w0.x, hc2[0]); hc2[1] = fma2(vv, w0.y, hc2[1]);
            hc2[2] = fma2(vv, w1.x, hc2[2]); hc2[3] = fma2(vv, w1.y, hc2[3]);
            hc2[4] = fma2(vv, w2.x, hc2[4]); hc2[5] = fma2(vv, w2.y, hc2[5]);
            hc2[6] = fma2(vv, w3.x, hc2[6]); hc2[7] = fma2(vv, w3.y, hc2[7]);
        }
        #pragma unroll
        for (int i = 0; i < ED; ++i) {
            const u64 vv = dup2(ro[i]);
            const ulonglong2* wr = reinterpret_cast<const ulonglong2*>(&sWpsi1[(ED + i) * HP + base]);
            const ulonglong2 w0 = wr[0], w1 = wr[1], w2 = wr[2], w3 = wr[3];
            hc2[0] = fma2(vv, w0.x, hc2[0]); hc2[1] = fma2(vv, w0.y, hc2[1]);
            hc2[2] = fma2(vv, w1.x, hc2[2]); hc2[3] = fma2(vv, w1.y, hc2[3]);
            hc2[4] = fma2(vv, w2.x, hc2[4]); hc2[5] = fma2(vv, w2.y, hc2[5]);
            hc2[6] = fma2(vv, w3.x, hc2[6]); hc2[7] = fma2(vv, w3.y, hc2[7]);
        }
        {
            const float gs[4] = { g0, g1, g2, g3 };
            #pragma unroll
            for (int k = 0; k < 4; ++k) {
                const u64 vv = dup2(gs[k]);
                const ulonglong2* wr = reinterpret_cast<const ulonglong2*>(&sWpsi1[(2 * ED + k) * HP + base]);
                const ulonglong2 w0 = wr[0], w1 = wr[1], w2 = wr[2], w3 = wr[3];
                hc2[0] = fma2(vv, w0.x, hc2[0]); hc2[1] = fma2(vv, w0.y, hc2[1]);
                hc2[2] = fma2(vv, w1.x, hc2[2]); hc2[3] = fma2(vv, w1.y, hc2[3]);
                hc2[4] = fma2(vv, w2.x, hc2[4]); hc2[5] = fma2(vv, w2.y, hc2[5]);
                hc2[6] = fma2(vv, w3.x, hc2[6]); hc2[7] = fma2(vv, w3.y, hc2[7]);
            }
        }
        #pragma unroll
        for (int q = 0; q < 8; ++q) {
            float u, v; unpack2(hc2[q], u, v);
            u = fmaxf(u, 0.f); v = fmaxf(v, 0.f);
            const u64 wu = *reinterpret_cast<const u64*>(&sWpsi2[2 * (base + 2 * q)]);
            const u64 wv = *reinterpret_cast<const u64*>(&sWpsi2[2 * (base + 2 * q + 1)]);
            acc2 = fma2(dup2(u), wu, acc2);
            acc2 = fma2(dup2(v), wv, acc2);
        }
    }

    float a0, a1;
    unpack2(acc2, a0, a1);
    a0 = fmaf(2.0f, tanhf(a0), bx);
    a1 = fmaf(2.0f, tanhf(a1), by);

    const float inv = fmaxf(fmaxf(fabsf(a0), fabsf(a1)) * 0.5f, 1.0f);
    const float r   = __fdividef(1.0f, inv);
    float2 res;
    res.x = a0 * r;
    res.y = a1 * r;
    reinterpret_cast<float2*>(out)[t] = res;
}

extern "C" void kernel_launch(void* const* d_in, const int* in_sizes, int n_in,
                              void* d_out, int out_size) {
    const float* x     = (const float*)d_in[0];
    const float* Wp1n  = (const float*)d_in[1];
    const float* bp1n  = (const float*)d_in[2];
    const float* Wp2n  = (const float*)d_in[3];
    const float* bp2n  = (const float*)d_in[4];
    const float* Wr1n  = (const float*)d_in[5];
    const float* br1n  = (const float*)d_in[6];
    const float* Wr2n  = (const float*)d_in[7];
    const float* br2n  = (const float*)d_in[8];
    const float* Wp1o  = (const float*)d_in[9];
    const float* bp1o  = (const float*)d_in[10];
    const float* Wp2o  = (const float*)d_in[11];
    const float* bp2o  = (const float*)d_in[12];
    const float* Wr1o  = (const float*)d_in[13];
    const float* br1o  = (const float*)d_in[14];
    const float* Wr2o  = (const float*)d_in[15];
    const float* br2o  = (const float*)d_in[16];
    const float* Wpsi1 = (const float*)d_in[17];
    const float* bpsi1 = (const float*)d_in[18];
    const float* Wpsi2 = (const float*)d_in[19];
    const float* bpsi2 = (const float*)d_in[20];
    float* out = (float*)d_out;

    const int nb = in_sizes[0] / XC;

    dim3 tg((nb + 31) / 32, (XC + 31) / 32);
    transpose_kernel<<<tg, 256>>>(x, nb);

    const int threads = 256;
    const int blocks = (nb + threads - 1) / threads;
    bnet_kernel<<<blocks, threads>>>(
        Wp1n, bp1n, Wp2n, bp2n, Wr1n, br1n, Wr2n, br2n,
        Wp1o, bp1o, Wp2o, bp2o, Wr1o, br1o, Wr2o, br2o,
        Wpsi1, bpsi1, Wpsi2, bpsi2, out, nb);
}

// round 8
// speedup vs baseline: 1.1966x; 1.1966x over previous
#include <cuda_runtime.h>
#include <math.h>

#define NNB  16
#define NOB  8
#define SDIM 4
#define H1   64
#define ED   16
#define HP   64
#define XC   85      // 1 + 4 + 64 + 16
#define BMAX 131072
#define TPB  128
#define NSM  148

// SoA scratch: xT[f][b], stride BMAX
__device__ float g_xT[XC * BMAX];

// ---------------- transpose kernel: x[B][85] -> g_xT[85][BMAX] ----------------
__global__ void __launch_bounds__(256)
transpose_kernel(const float* __restrict__ x, int nb)
{
    __shared__ float tile[32][33];
    const int bBase = blockIdx.x * 32;
    const int fBase = blockIdx.y * 32;
    const int tx = threadIdx.x & 31;
    const int ty = threadIdx.x >> 5;

    #pragma unroll
    for (int r = ty; r < 32; r += 8) {
        const int b = bBase + r, f = fBase + tx;
        if (b < nb && f < XC)
            tile[r][tx] = x[(size_t)b * XC + f];
    }
    __syncthreads();
    #pragma unroll
    for (int r = ty; r < 32; r += 8) {
        const int f = fBase + r, b = bBase + tx;
        if (b < nb && f < XC)
            g_xT[(size_t)f * BMAX + b] = tile[tx][r];
    }
}

__device__ __forceinline__ void barrier_acc(float e0, float e1, float D,
                                            float& bx, float& by) {
    const float px = -e0, py = -e1;
    const float q  = fmaf(px, px, py * py);
    const float rq = rsqrtf(q);
    const float nrm = q * rq;
    const float s  = 0.05f * __fdividef(1.0f, nrm * (nrm - D));
    bx = fmaf(s, px, bx);
    by = fmaf(s, py, by);
}

__global__ void __launch_bounds__(TPB, 4)
bnet_kernel(const float* __restrict__ Wp1n, const float* __restrict__ bp1n,
            const float* __restrict__ Wp2n, const float* __restrict__ bp2n,
            const float* __restrict__ Wr1n, const float* __restrict__ br1n,
            const float* __restrict__ Wr2n, const float* __restrict__ br2n,
            const float* __restrict__ Wp1o, const float* __restrict__ bp1o,
            const float* __restrict__ Wp2o, const float* __restrict__ bp2o,
            const float* __restrict__ Wr1o, const float* __restrict__ br1o,
            const float* __restrict__ Wr2o, const float* __restrict__ br2o,
            const float* __restrict__ Wpsi1, const float* __restrict__ bpsi1,
            const float* __restrict__ Wpsi2, const float* __restrict__ bpsi2,
            float* __restrict__ out, int nb)
{
    __shared__ __align__(16) float sWp1n_t[H1 * 4];   // [h][4]
    __shared__ __align__(16) float sbp1n[H1];
    __shared__ __align__(16) float sWp2n[H1 * ED];
    __shared__ __align__(16) float sbp2n[ED];
    __shared__ __align__(16) float sWr1n[ED * H1];
    __shared__ __align__(16) float sbr1n[H1];
    __shared__ __align__(16) float sWr2n[H1 * ED];
    __shared__ __align__(16) float sbr2n[ED];
    __shared__ __align__(16) float sWp1o_t[H1 * 2];   // [h][2]
    __shared__ __align__(16) float sbp1o[H1];
    __shared__ __align__(16) float sWp2o[H1 * ED];
    __shared__ __align__(16) float sbp2o[ED];
    __shared__ __align__(16) float sWr1o[ED * H1];
    __shared__ __align__(16) float sbr1o[H1];
    __shared__ __align__(16) float sWr2o[H1 * ED];
    __shared__ __align__(16) float sbr2o[ED];
    __shared__ __align__(16) float sWpsi1[(2 * ED + SDIM) * HP];
    __shared__ __align__(16) float sbpsi1[HP];
    __shared__ __align__(16) float sWpsi2[HP * 2];
    __shared__ __align__(16) float sbpsi2[2];

    // ---- staging (once per persistent CTA) ----
    for (int i = threadIdx.x; i < H1 * 4; i += TPB) {
        int h = i >> 2, k = i & 3;
        sWp1n_t[i] = Wp1n[k * H1 + h];
    }
    for (int i = threadIdx.x; i < H1 * 2; i += TPB) {
        int h = i >> 1, k = i & 1;
        sWp1o_t[i] = Wp1o[k * H1 + h];
    }
    {
        float* dsts[18]       = { sbp1n, sWp2n, sbp2n, sWr1n, sbr1n, sWr2n, sbr2n,
                                  sbp1o, sWp2o, sbp2o, sWr1o, sbr1o, sWr2o, sbr2o,
                                  sWpsi1, sbpsi1, sWpsi2, sbpsi2 };
        const float* srcs[18] = { bp1n, Wp2n, bp2n, Wr1n, br1n, Wr2n, br2n,
                                  bp1o, Wp2o, bp2o, Wr1o, br1o, Wr2o, br2o,
                                  Wpsi1, bpsi1, Wpsi2, bpsi2 };
        const int ns[18]      = { H1, H1*ED, ED, ED*H1, H1, H1*ED, ED,
                                  H1, H1*ED, ED, ED*H1, H1, H1*ED, ED,
                                  (2*ED+SDIM)*HP, HP, HP*2, 2 };
        for (int a = 0; a < 18; ++a)
            for (int i = threadIdx.x; i < ns[a]; i += TPB)
                dsts[a][i] = srcs[a][i];
    }
    __syncthreads();

    const int stride = gridDim.x * TPB;

    for (int t = blockIdx.x * TPB + threadIdx.x; t < nb; t += stride) {

        float bx = 0.f, by = 0.f;
        float rn[ED], ro[ED], sp[ED];

        // ======================= neighbor deep-set =======================
        // 16 neighbors in 4 groups of 4; each weight LDS feeds 16 FMAs.
        {
            float hs[H1];
            #pragma unroll
            for (int h = 0; h < H1; ++h) hs[h] = 0.f;

            const float* xb = g_xT + 5 * BMAX + t;   // neighbor features 5..68
            float e[16], en[16];
            #pragma unroll
            for (int i = 0; i < 16; ++i) e[i] = xb[(size_t)i * BMAX];

            #pragma unroll 1
            for (int g = 0; g < 4; ++g) {
                if (g < 3) {
                    const float* xn = xb + (size_t)(16 * (g + 1)) * BMAX;
                    #pragma unroll
                    for (int i = 0; i < 16; ++i) en[i] = xn[(size_t)i * BMAX];
                }
                #pragma unroll
                for (int k = 0; k < 4; ++k)
                    barrier_acc(e[4 * k + 0], e[4 * k + 1], 0.3f, bx, by);

                #pragma unroll
                for (int h = 0; h < H1; ++h) {
                    const float4 w = *reinterpret_cast<const float4*>(&sWp1n_t[h * 4]);
                    const float b = sbp1n[h];
                    float v0 = b, v1 = b, v2 = b, v3 = b;
                    v0 = fmaf(e[0],  w.x, v0); v0 = fmaf(e[1],  w.y, v0);
                    v0 = fmaf(e[2],  w.z, v0); v0 = fmaf(e[3],  w.w, v0);
                    v1 = fmaf(e[4],  w.x, v1); v1 = fmaf(e[5],  w.y, v1);
                    v1 = fmaf(e[6],  w.z, v1); v1 = fmaf(e[7],  w.w, v1);
                    v2 = fmaf(e[8],  w.x, v2); v2 = fmaf(e[9],  w.y, v2);
                    v2 = fmaf(e[10], w.z, v2); v2 = fmaf(e[11], w.w, v2);
                    v3 = fmaf(e[12], w.x, v3); v3 = fmaf(e[13], w.y, v3);
                    v3 = fmaf(e[14], w.z, v3); v3 = fmaf(e[15], w.w, v3);
                    hs[h] += (fmaxf(v0, 0.f) + fmaxf(v1, 0.f))
                           + (fmaxf(v2, 0.f) + fmaxf(v3, 0.f));
                }
                #pragma unroll
                for (int i = 0; i < 16; ++i) e[i] = en[i];
            }

            #pragma unroll
            for (int o = 0; o < ED; ++o) sp[o] = (float)NNB * sbp2n[o];
            #pragma unroll
            for (int h = 0; h < H1; ++h) {
                const float v = hs[h];
                #pragma unroll
                for (int o = 0; o < ED; ++o) sp[o] = fmaf(v, sWp2n[h * ED + o], sp[o]);
            }
        }
        // rho_n (hidden chunked by 16)
        #pragma unroll
        for (int o = 0; o < ED; ++o) rn[o] = sbr2n[o];
        #pragma unroll 1
        for (int c = 0; c < 4; ++c) {
            const int base = c * 16;
            float hc[16];
            #pragma unroll
            for (int h = 0; h < 16; ++h) hc[h] = sbr1n[base + h];
            #pragma unroll
            for (int i = 0; i < ED; ++i) {
                const float v = sp[i];
                #pragma unroll
                for (int h = 0; h < 16; ++h)
                    hc[h] = fmaf(v, sWr1n[i * H1 + base + h], hc[h]);
            }
            #pragma unroll
            for (int h = 0; h < 16; ++h) {
                const float v = fmaxf(hc[h], 0.f);
                #pragma unroll
                for (int o = 0; o < ED; ++o)
                    rn[o] = fmaf(v, sWr2n[(base + h) * ED + o], rn[o]);
            }
        }

        // ======================= obstacle deep-set =======================
        {
            float e[16];
            const float* xo = g_xT + 69 * BMAX + t;   // obstacle features 69..84
            #pragma unroll
            for (int i = 0; i < 16; ++i) e[i] = xo[(size_t)i * BMAX];

            #pragma unroll
            for (int k = 0; k < 8; ++k)
                barrier_acc(e[2 * k + 0], e[2 * k + 1], 0.3f, bx, by);

            float hs[H1];
            #pragma unroll
            for (int h = 0; h < H1; ++h) {
                const float2 w = *reinterpret_cast<const float2*>(&sWp1o_t[h * 2]);
                const float b = sbp1o[h];
                float acc0 = 0.f, acc1 = 0.f;
                #pragma unroll
                for (int k = 0; k < 8; k += 2) {
                    float va = b, vb = b;
                    va = fmaf(e[2 * k + 0], w.x, va);
                    va = fmaf(e[2 * k + 1], w.y, va);
                    vb = fmaf(e[2 * k + 2], w.x, vb);
                    vb = fmaf(e[2 * k + 3], w.y, vb);
                    acc0 += fmaxf(va, 0.f);
                    acc1 += fmaxf(vb, 0.f);
                }
                hs[h] = acc0 + acc1;
            }

            #pragma unroll
            for (int o = 0; o < ED; ++o) sp[o] = (float)NOB * sbp2o[o];
            #pragma unroll
            for (int h = 0; h < H1; ++h) {
                const float v = hs[h];
                #pragma unroll
                for (int o = 0; o < ED; ++o) sp[o] = fmaf(v, sWp2o[h * ED + o], sp[o]);
            }
        }
        #pragma unroll
        for (int o = 0; o < ED; ++o) ro[o] = sbr2o[o];
        #pragma unroll 1
        for (int c = 0; c < 4; ++c) {
            const int base = c * 16;
            float hc[16];
            #pragma unroll
            for (int h = 0; h < 16; ++h) hc[h] = sbr1o[base + h];
            #pragma unroll
            for (int i = 0; i < ED; ++i) {
                const float v = sp[i];
                #pragma unroll
                for (int h = 0; h < 16; ++h)
                    hc[h] = fmaf(v, sWr1o[i * H1 + base + h], hc[h]);
            }
            #pragma unroll
            for (int h = 0; h < 16; ++h) {
                const float v = fmaxf(hc[h], 0.f);
                #pragma unroll
                for (int o = 0; o < ED; ++o)
                    ro[o] = fmaf(v, sWr2o[(base + h) * ED + o], ro[o]);
            }
        }

        // ======================= psi head (chunked) =======================
        const float g0 = g_xT[1 * BMAX + t], g1 = g_xT[2 * BMAX + t];
        const float g2 = g_xT[3 * BMAX + t], g3 = g_xT[4 * BMAX + t];
        float a0 = sbpsi2[0], a1 = sbpsi2[1];
        #pragma unroll 1
        for (int c = 0; c < 4; ++c) {
            const int base = c * 16;
            float hc[16];
            #pragma unroll
            for (int h = 0; h < 16; ++h) hc[h] = sbpsi1[base + h];
            #pragma unroll
            for (int i = 0; i < ED; ++i) {
                const float v = rn[i];
                #pragma unroll
                for (int h = 0; h < 16; ++h)
                    hc[h] = fmaf(v, sWpsi1[i * HP + base + h], hc[h]);
            }
            #pragma unroll
            for (int i = 0; i < ED; ++i) {
                const float v = ro[i];
                #pragma unroll
                for (int h = 0; h < 16; ++h)
                    hc[h] = fmaf(v, sWpsi1[(ED + i) * HP + base + h], hc[h]);
            }
            #pragma unroll
            for (int h = 0; h < 16; ++h) {
                float v = hc[h];
                v = fmaf(g0, sWpsi1[(2 * ED + 0) * HP + base + h], v);
                v = fmaf(g1, sWpsi1[(2 * ED + 1) * HP + base + h], v);
                v = fmaf(g2, sWpsi1[(2 * ED + 2) * HP + base + h], v);
                v = fmaf(g3, sWpsi1[(2 * ED + 3) * HP + base + h], v);
                v = fmaxf(v, 0.f);
                a0 = fmaf(v, sWpsi2[2 * (base + h) + 0], a0);
                a1 = fmaf(v, sWpsi2[2 * (base + h) + 1], a1);
            }
        }

        a0 = fmaf(2.0f, tanhf(a0), bx);
        a1 = fmaf(2.0f, tanhf(a1), by);

        const float inv = fmaxf(fmaxf(fabsf(a0), fabsf(a1)) * 0.5f, 1.0f);
        const float r   = __fdividef(1.0f, inv);
        float2 res;
        res.x = a0 * r;
        res.y = a1 * r;
        reinterpret_cast<float2*>(out)[t] = res;
    }
}

extern "C" void kernel_launch(void* const* d_in, const int* in_sizes, int n_in,
                              void* d_out, int out_size) {
    const float* x     = (const float*)d_in[0];
    const float* Wp1n  = (const float*)d_in[1];
    const float* bp1n  = (const float*)d_in[2];
    const float* Wp2n  = (const float*)d_in[3];
    const float* bp2n  = (const float*)d_in[4];
    const float* Wr1n  = (const float*)d_in[5];
    const float* br1n  = (const float*)d_in[6];
    const float* Wr2n  = (const float*)d_in[7];
    const float* br2n  = (const float*)d_in[8];
    const float* Wp1o  = (const float*)d_in[9];
    const float* bp1o  = (const float*)d_in[10];
    const float* Wp2o  = (const float*)d_in[11];
    const float* bp2o  = (const float*)d_in[12];
    const float* Wr1o  = (const float*)d_in[13];
    const float* br1o  = (const float*)d_in[14];
    const float* Wr2o  = (const float*)d_in[15];
    const float* br2o  = (const float*)d_in[16];
    const float* Wpsi1 = (const float*)d_in[17];
    const float* bpsi1 = (const float*)d_in[18];
    const float* Wpsi2 = (const float*)d_in[19];
    const float* bpsi2 = (const float*)d_in[20];
    float* out = (float*)d_out;

    const int nb = in_sizes[0] / XC;

    dim3 tg((nb + 31) / 32, (XC + 31) / 32);
    transpose_kernel<<<tg, 256>>>(x, nb);

    int blocks = NSM * 4;                       // persistent, 4 CTAs/SM
    const int needed = (nb + TPB - 1) / TPB;
    if (blocks > needed) blocks = needed;
    bnet_kernel<<<blocks, TPB>>>(
        Wp1n, bp1n, Wp2n, bp2n, Wr1n, br1n, Wr2n, br2n,
        Wp1o, bp1o, Wp2o, bp2o, Wr1o, br1o, Wr2o, br2o,
        Wpsi1, bpsi1, Wpsi2, bpsi2, out, nb);
}

// round 9
// speedup vs baseline: 1.2288x; 1.0269x over previous
#include <cuda_runtime.h>
#include <math.h>

#define NNB  16
#define NOB  8
#define SDIM 4
#define H1   64
#define ED   16
#define HP   64
#define XC   85      // 1 + 4 + 64 + 16
#define BMAX 131072
#define NGRP 21      // 16 neighbor groups + 4 obstacle-pair groups + 1 goal group

// packed SoA scratch: g_xP[(grp*BMAX + b)*4 + c], 84*BMAX floats
__device__ float g_xP[XC * BMAX];

// ---------------- pack kernel: x[B][85] -> float4 entity groups ----------------
__global__ void __launch_bounds__(256)
pack_kernel(const float* __restrict__ x, int nb)
{
    __shared__ float buf[32][88];
    const int bBase = blockIdx.x * 32;

    for (int i = threadIdx.x; i < 32 * 85; i += 256) {
        const int r = i / 85, f = i - 85 * r;
        const int b = bBase + r;
        buf[r][f] = (b < nb) ? x[(size_t)b * 85 + f] : 0.f;
    }
    __syncthreads();

    const int bl = threadIdx.x & 31;
    const int b  = bBase + bl;
    if (b < nb) {
        for (int g = threadIdx.x >> 5; g < NGRP; g += 8) {
            const int fb = (g < 16) ? (5 + 4 * g) : (g < 20 ? (69 + 4 * (g - 16)) : 1);
            float4 v;
            v.x = buf[bl][fb];     v.y = buf[bl][fb + 1];
            v.z = buf[bl][fb + 2]; v.w = buf[bl][fb + 3];
            *reinterpret_cast<float4*>(&g_xP[((size_t)g * BMAX + b) * 4]) = v;
        }
    }
}

__device__ __forceinline__ void barrier_acc(float e0, float e1, float D,
                                            float& bx, float& by) {
    const float px = -e0, py = -e1;
    const float q  = fmaf(px, px, py * py);
    const float rq = rsqrtf(q);
    const float nrm = q * rq;
    const float s  = 0.05f * __fdividef(1.0f, nrm * (nrm - D));
    bx = fmaf(s, px, bx);
    by = fmaf(s, py, by);
}

__global__ void __launch_bounds__(256, 2)
bnet_kernel(const float* __restrict__ Wp1n, const float* __restrict__ bp1n,
            const float* __restrict__ Wp2n, const float* __restrict__ bp2n,
            const float* __restrict__ Wr1n, const float* __restrict__ br1n,
            const float* __restrict__ Wr2n, const float* __restrict__ br2n,
            const float* __restrict__ Wp1o, const float* __restrict__ bp1o,
            const float* __restrict__ Wp2o, const float* __restrict__ bp2o,
            const float* __restrict__ Wr1o, const float* __restrict__ br1o,
            const float* __restrict__ Wr2o, const float* __restrict__ br2o,
            const float* __restrict__ Wpsi1, const float* __restrict__ bpsi1,
            const float* __restrict__ Wpsi2, const float* __restrict__ bpsi2,
            float* __restrict__ out, int nb)
{
    __shared__ __align__(16) float sWp1n_t[H1 * 4];   // [h][4]
    __shared__ __align__(16) float sbp1n[H1];
    __shared__ __align__(16) float sWp2n[H1 * ED];
    __shared__ __align__(16) float sbp2n[ED];         // pre-scaled by NNB
    __shared__ __align__(16) float sWr1n[ED * H1];
    __shared__ __align__(16) float sbr1n[H1];
    __shared__ __align__(16) float sWr2n[H1 * ED];
    __shared__ __align__(16) float sbr2n[ED];
    __shared__ __align__(16) float sWp1o_t[H1 * 2];   // [h][2]
    __shared__ __align__(16) float sbp1o[H1];
    __shared__ __align__(16) float sWp2o[H1 * ED];
    __shared__ __align__(16) float sbp2o[ED];         // pre-scaled by NOB
    __shared__ __align__(16) float sWr1o[ED * H1];
    __shared__ __align__(16) float sbr1o[H1];
    __shared__ __align__(16) float sWr2o[H1 * ED];
    __shared__ __align__(16) float sbr2o[ED];
    __shared__ __align__(16) float sWpsi1[(2 * ED + SDIM) * HP];
    __shared__ __align__(16) float sbpsi1[HP];
    __shared__ __align__(16) float sWpsi2[HP * 2];
    __shared__ __align__(16) float sbpsi2[2];

    // ---- staging ----
    for (int i = threadIdx.x; i < H1 * 4; i += 256) {
        int h = i >> 2, k = i & 3;
        sWp1n_t[i] = Wp1n[k * H1 + h];
    }
    for (int i = threadIdx.x; i < H1 * 2; i += 256) {
        int h = i >> 1, k = i & 1;
        sWp1o_t[i] = Wp1o[k * H1 + h];
    }
    for (int i = threadIdx.x; i < ED; i += 256) {
        sbp2n[i] = (float)NNB * bp2n[i];
        sbp2o[i] = (float)NOB * bp2o[i];
    }
    {
        float* dsts[16]       = { sbp1n, sWp2n, sWr1n, sbr1n, sWr2n, sbr2n,
                                  sbp1o, sWp2o, sWr1o, sbr1o, sWr2o, sbr2o,
                                  sWpsi1, sbpsi1, sWpsi2, sbpsi2 };
        const float* srcs[16] = { bp1n, Wp2n, Wr1n, br1n, Wr2n, br2n,
                                  bp1o, Wp2o, Wr1o, br1o, Wr2o, br2o,
                                  Wpsi1, bpsi1, Wpsi2, bpsi2 };
        const int ns[16]      = { H1, H1*ED, ED*H1, H1, H1*ED, ED,
                                  H1, H1*ED, ED*H1, H1, H1*ED, ED,
                                  (2*ED+SDIM)*HP, HP, HP*2, 2 };
        for (int a = 0; a < 16; ++a)
            for (int i = threadIdx.x; i < ns[a]; i += 256)
                dsts[a][i] = srcs[a][i];
    }
    __syncthreads();

    const int t = blockIdx.x * blockDim.x + threadIdx.x;
    if (t >= nb) return;

    const float4* xp = reinterpret_cast<const float4*>(g_xP);  // [(grp*BMAX + t)]

    float bx = 0.f, by = 0.f;
    float rn[ED], ro[ED], sp[ED];

    // ======================= neighbor deep-set =======================
    // 16 neighbors in 2 groups of 8; each weight LDS feeds 32 FMAs.
    {
        float hs[H1];
        #pragma unroll
        for (int h = 0; h < H1; ++h) hs[h] = 0.f;

        #pragma unroll 1
        for (int g = 0; g < 2; ++g) {
            float e[32];
            #pragma unroll
            for (int j = 0; j < 8; ++j) {
                const float4 v = xp[(size_t)(8 * g + j) * BMAX + t];
                e[4 * j + 0] = v.x; e[4 * j + 1] = v.y;
                e[4 * j + 2] = v.z; e[4 * j + 3] = v.w;
            }
            #pragma unroll
            for (int k = 0; k < 8; ++k)
                barrier_acc(e[4 * k + 0], e[4 * k + 1], 0.3f, bx, by);

            #pragma unroll
            for (int h = 0; h < H1; ++h) {
                const float4 w = *reinterpret_cast<const float4*>(&sWp1n_t[h * 4]);
                const float b = sbp1n[h];
                float v0 = b, v1 = b, v2 = b, v3 = b;
                float v4 = b, v5 = b, v6 = b, v7 = b;
                v0 = fmaf(e[0],  w.x, v0); v0 = fmaf(e[1],  w.y, v0);
                v0 = fmaf(e[2],  w.z, v0); v0 = fmaf(e[3],  w.w, v0);
                v1 = fmaf(e[4],  w.x, v1); v1 = fmaf(e[5],  w.y, v1);
                v1 = fmaf(e[6],  w.z, v1); v1 = fmaf(e[7],  w.w, v1);
                v2 = fmaf(e[8],  w.x, v2); v2 = fmaf(e[9],  w.y, v2);
                v2 = fmaf(e[10], w.z, v2); v2 = fmaf(e[11], w.w, v2);
                v3 = fmaf(e[12], w.x, v3); v3 = fmaf(e[13], w.y, v3);
                v3 = fmaf(e[14], w.z, v3); v3 = fmaf(e[15], w.w, v3);
                v4 = fmaf(e[16], w.x, v4); v4 = fmaf(e[17], w.y, v4);
                v4 = fmaf(e[18], w.z, v4); v4 = fmaf(e[19], w.w, v4);
                v5 = fmaf(e[20], w.x, v5); v5 = fmaf(e[21], w.y, v5);
                v5 = fmaf(e[22], w.z, v5); v5 = fmaf(e[23], w.w, v5);
                v6 = fmaf(e[24], w.x, v6); v6 = fmaf(e[25], w.y, v6);
                v6 = fmaf(e[26], w.z, v6); v6 = fmaf(e[27], w.w, v6);
                v7 = fmaf(e[28], w.x, v7); v7 = fmaf(e[29], w.y, v7);
                v7 = fmaf(e[30], w.z, v7); v7 = fmaf(e[31], w.w, v7);
                const float s0 = (fmaxf(v0, 0.f) + fmaxf(v1, 0.f))
                               + (fmaxf(v2, 0.f) + fmaxf(v3, 0.f));
                const float s1 = (fmaxf(v4, 0.f) + fmaxf(v5, 0.f))
                               + (fmaxf(v6, 0.f) + fmaxf(v7, 0.f));
                hs[h] += s0 + s1;
            }
        }

        #pragma unroll
        for (int o = 0; o < ED; ++o) sp[o] = sbp2n[o];
        #pragma unroll
        for (int h = 0; h < H1; ++h) {
            const float v = hs[h];
            #pragma unroll
            for (int o = 0; o < ED; ++o) sp[o] = fmaf(v, sWp2n[h * ED + o], sp[o]);
        }
    }
    // rho_n (hidden chunked by 16)
    #pragma unroll
    for (int o = 0; o < ED; ++o) rn[o] = sbr2n[o];
    #pragma unroll 1
    for (int c = 0; c < 4; ++c) {
        const int base = c * 16;
        float hc[16];
        #pragma unroll
        for (int h = 0; h < 16; ++h) hc[h] = sbr1n[base + h];
        #pragma unroll
        for (int i = 0; i < ED; ++i) {
            const float v = sp[i];
            #pragma unroll
            for (int h = 0; h < 16; ++h)
                hc[h] = fmaf(v, sWr1n[i * H1 + base + h], hc[h]);
        }
        #pragma unroll
        for (int h = 0; h < 16; ++h) {
            const float v = fmaxf(hc[h], 0.f);
            #pragma unroll
            for (int o = 0; o < ED; ++o)
                rn[o] = fmaf(v, sWr2n[(base + h) * ED + o], rn[o]);
        }
    }

    // ======================= obstacle deep-set =======================
    {
        float e[16];
        #pragma unroll
        for (int j = 0; j < 4; ++j) {
            const float4 v = xp[(size_t)(16 + j) * BMAX + t];
            e[4 * j + 0] = v.x; e[4 * j + 1] = v.y;
            e[4 * j + 2] = v.z; e[4 * j + 3] = v.w;
        }
        #pragma unroll
        for (int k = 0; k < 8; ++k)
            barrier_acc(e[2 * k + 0], e[2 * k + 1], 0.3f, bx, by);

        float hs[H1];
        #pragma unroll
        for (int h = 0; h < H1; ++h) {
            const float2 w = *reinterpret_cast<const float2*>(&sWp1o_t[h * 2]);
            const float b = sbp1o[h];
            float acc0 = 0.f, acc1 = 0.f;
            #pragma unroll
            for (int k = 0; k < 8; k += 2) {
                float va = b, vb = b;
                va = fmaf(e[2 * k + 0], w.x, va);
                va = fmaf(e[2 * k + 1], w.y, va);
                vb = fmaf(e[2 * k + 2], w.x, vb);
                vb = fmaf(e[2 * k + 3], w.y, vb);
                acc0 += fmaxf(va, 0.f);
                acc1 += fmaxf(vb, 0.f);
            }
            hs[h] = acc0 + acc1;
        }

        #pragma unroll
        for (int o = 0; o < ED; ++o) sp[o] = sbp2o[o];
        #pragma unroll
        for (int h = 0; h < H1; ++h) {
            const float v = hs[h];
            #pragma unroll
            for (int o = 0; o < ED; ++o) sp[o] = fmaf(v, sWp2o[h * ED + o], sp[o]);
        }
    }
    #pragma unroll
    for (int o = 0; o < ED; ++o) ro[o] = sbr2o[o];
    #pragma unroll 1
    for (int c = 0; c < 4; ++c) {
        const int base = c * 16;
        float hc[16];
        #pragma unroll
        for (int h = 0; h < 16; ++h) hc[h] = sbr1o[base + h];
        #pragma unroll
        for (int i = 0; i < ED; ++i) {
            const float v = sp[i];
            #pragma unroll
            for (int h = 0; h < 16; ++h)
                hc[h] = fmaf(v, sWr1o[i * H1 + base + h], hc[h]);
        }
        #pragma unroll
        for (int h = 0; h < 16; ++h) {
            const float v = fmaxf(hc[h], 0.f);
            #pragma unroll
            for (int o = 0; o < ED; ++o)
                ro[o] = fmaf(v, sWr2o[(base + h) * ED + o], ro[o]);
        }
    }

    // ======================= psi head (chunked) =======================
    const float4 gv = xp[(size_t)20 * BMAX + t];
    const float g0 = gv.x, g1 = gv.y, g2 = gv.z, g3 = gv.w;
    float a0 = sbpsi2[0], a1 = sbpsi2[1];
    #pragma unroll 1
    for (int c = 0; c < 4; ++c) {
        const int base = c * 16;
        float hc[16];
        #pragma unroll
        for (int h = 0; h < 16; ++h) hc[h] = sbpsi1[base + h];
        #pragma unroll
        for (int i = 0; i < ED; ++i) {
            const float v = rn[i];
            #pragma unroll
            for (int h = 0; h < 16; ++h)
                hc[h] = fmaf(v, sWpsi1[i * HP + base + h], hc[h]);
        }
        #pragma unroll
        for (int i = 0; i < ED; ++i) {
            const float v = ro[i];
            #pragma unroll
            for (int h = 0; h < 16; ++h)
                hc[h] = fmaf(v, sWpsi1[(ED + i) * HP + base + h], hc[h]);
        }
        #pragma unroll
        for (int h = 0; h < 16; ++h) {
            float v = hc[h];
            v = fmaf(g0, sWpsi1[(2 * ED + 0) * HP + base + h], v);
            v = fmaf(g1, sWpsi1[(2 * ED + 1) * HP + base + h], v);
            v = fmaf(g2, sWpsi1[(2 * ED + 2) * HP + base + h], v);
            v = fmaf(g3, sWpsi1[(2 * ED + 3) * HP + base + h], v);
            v = fmaxf(v, 0.f);
            a0 = fmaf(v, sWpsi2[2 * (base + h) + 0], a0);
            a1 = fmaf(v, sWpsi2[2 * (base + h) + 1], a1);
        }
    }

    a0 = fmaf(2.0f, tanhf(a0), bx);
    a1 = fmaf(2.0f, tanhf(a1), by);

    const float inv = fmaxf(fmaxf(fabsf(a0), fabsf(a1)) * 0.5f, 1.0f);
    const float r   = __fdividef(1.0f, inv);
    float2 res;
    res.x = a0 * r;
    res.y = a1 * r;
    reinterpret_cast<float2*>(out)[t] = res;
}

extern "C" void kernel_launch(void* const* d_in, const int* in_sizes, int n_in,
                              void* d_out, int out_size) {
    const float* x     = (const float*)d_in[0];
    const float* Wp1n  = (const float*)d_in[1];
    const float* bp1n  = (const float*)d_in[2];
    const float* Wp2n  = (const float*)d_in[3];
    const float* bp2n  = (const float*)d_in[4];
    const float* Wr1n  = (const float*)d_in[5];
    const float* br1n  = (const float*)d_in[6];
    const float* Wr2n  = (const float*)d_in[7];
    const float* br2n  = (const float*)d_in[8];
    const float* Wp1o  = (const float*)d_in[9];
    const float* bp1o  = (const float*)d_in[10];
    const float* Wp2o  = (const float*)d_in[11];
    const float* bp2o  = (const float*)d_in[12];
    const float* Wr1o  = (const float*)d_in[13];
    const float* br1o  = (const float*)d_in[14];
    const float* Wr2o  = (const float*)d_in[15];
    const float* br2o  = (const float*)d_in[16];
    const float* Wpsi1 = (const float*)d_in[17];
    const float* bpsi1 = (const float*)d_in[18];
    const float* Wpsi2 = (const float*)d_in[19];
    const float* bpsi2 = (const float*)d_in[20];
    float* out = (float*)d_out;

    const int nb = in_sizes[0] / XC;

    pack_kernel<<<(nb + 31) / 32, 256>>>(x, nb);

    const int threads = 256;
    const int blocks = (nb + threads - 1) / threads;
    bnet_kernel<<<blocks, threads>>>(
        Wp1n, bp1n, Wp2n, bp2n, Wr1n, br1n, Wr2n, br2n,
        Wp1o, bp1o, Wp2o, bp2o, Wr1o, br1o, Wr2o, br2o,
        Wpsi1, bpsi1, Wpsi2, bpsi2, out, nb);
}

// round 10
// speedup vs baseline: 1.6748x; 1.3629x over previous
#include <cuda_runtime.h>
#include <math.h>

#define NNB  16
#define NOB  8
#define SDIM 4
#define H1   64
#define ED   16
#define HP   64
#define XC   85      // 1 + 4 + 64 + 16
#define BMAX 131072
#define NGRP 21      // 16 neighbor + 4 obstacle-pair + 1 goal group

// packed SoA scratch: g_xP[(grp*BMAX + b)*4 + c]
__device__ float g_xP[XC * BMAX];

// ---------------- all weights in constant memory (copied D2D at launch) ----------------
__constant__ float cWp1n[SDIM * H1];
__constant__ float cbp1n[H1];
__constant__ float cWp2n[H1 * ED];
__constant__ float cbp2n[ED];
__constant__ float cWr1n[ED * H1];
__constant__ float cbr1n[H1];
__constant__ float cWr2n[H1 * ED];
__constant__ float cbr2n[ED];
__constant__ float cWp1o[2 * H1];
__constant__ float cbp1o[H1];
__constant__ float cWp2o[H1 * ED];
__constant__ float cbp2o[ED];
__constant__ float cWr1o[ED * H1];
__constant__ float cbr1o[H1];
__constant__ float cWr2o[H1 * ED];
__constant__ float cbr2o[ED];
__constant__ float cWpsi1[(2 * ED + SDIM) * HP];
__constant__ float cbpsi1[HP];
__constant__ float cWpsi2[HP * 2];
__constant__ float cbpsi2[2];

// ---------------- pack kernel: x[B][85] -> float4 entity groups (conflict-free) ----------------
__global__ void __launch_bounds__(256)
pack_kernel(const float* __restrict__ x, int nb)
{
    __shared__ float buf[32][85];   // stride 85: gcd(85,32)=1 -> no bank conflicts
    const int bBase = blockIdx.x * 32;

    for (int i = threadIdx.x; i < 32 * 85; i += 256) {
        const int r = i / 85, f = i - 85 * r;
        const int b = bBase + r;
        buf[r][f] = (b < nb) ? x[(size_t)b * 85 + f] : 0.f;
    }
    __syncthreads();

    const int bl = threadIdx.x & 31;
    const int b  = bBase + bl;
    if (b < nb) {
        for (int g = threadIdx.x >> 5; g < NGRP; g += 8) {
            const int fb = (g < 16) ? (5 + 4 * g) : (g < 20 ? (69 + 4 * (g - 16)) : 1);
            float4 v;
            v.x = buf[bl][fb];     v.y = buf[bl][fb + 1];
            v.z = buf[bl][fb + 2]; v.w = buf[bl][fb + 3];
            *reinterpret_cast<float4*>(&g_xP[((size_t)g * BMAX + b) * 4]) = v;
        }
    }
}

__device__ __forceinline__ void barrier_acc(float e0, float e1, float D,
                                            float& bx, float& by) {
    const float px = -e0, py = -e1;
    const float q  = fmaf(px, px, py * py);
    const float rq = rsqrtf(q);
    const float nrm = q * rq;
    const float s  = 0.05f * __fdividef(1.0f, nrm * (nrm - D));
    bx = fmaf(s, px, bx);
    by = fmaf(s, py, by);
}

__global__ void __launch_bounds__(256, 2)
bnet_kernel(float* __restrict__ out, int nb)
{
    const int t = blockIdx.x * blockDim.x + threadIdx.x;
    if (t >= nb) return;

    const float4* xp = reinterpret_cast<const float4*>(g_xP);

    float bx = 0.f, by = 0.f;
    float rn[ED], ro[ED], sp[ED];

    // ======================= neighbor deep-set =======================
    {
        float hs[H1];
        #pragma unroll
        for (int h = 0; h < H1; ++h) hs[h] = 0.f;

        #pragma unroll 1
        for (int g = 0; g < 2; ++g) {
            float e[32];
            #pragma unroll
            for (int j = 0; j < 8; ++j) {
                const float4 v = xp[(size_t)(8 * g + j) * BMAX + t];
                e[4 * j + 0] = v.x; e[4 * j + 1] = v.y;
                e[4 * j + 2] = v.z; e[4 * j + 3] = v.w;
            }
            #pragma unroll
            for (int k = 0; k < 8; ++k)
                barrier_acc(e[4 * k + 0], e[4 * k + 1], 0.3f, bx, by);

            #pragma unroll
            for (int h = 0; h < H1; ++h) {
                const float w0 = cWp1n[0 * H1 + h];
                const float w1 = cWp1n[1 * H1 + h];
                const float w2 = cWp1n[2 * H1 + h];
                const float w3 = cWp1n[3 * H1 + h];
                const float b  = cbp1n[h];
                float v0 = b, v1 = b, v2 = b, v3 = b;
                float v4 = b, v5 = b, v6 = b, v7 = b;
                v0 = fmaf(e[0],  w0, v0); v0 = fmaf(e[1],  w1, v0);
                v0 = fmaf(e[2],  w2, v0); v0 = fmaf(e[3],  w3, v0);
                v1 = fmaf(e[4],  w0, v1); v1 = fmaf(e[5],  w1, v1);
                v1 = fmaf(e[6],  w2, v1); v1 = fmaf(e[7],  w3, v1);
                v2 = fmaf(e[8],  w0, v2); v2 = fmaf(e[9],  w1, v2);
                v2 = fmaf(e[10], w2, v2); v2 = fmaf(e[11], w3, v2);
                v3 = fmaf(e[12], w0, v3); v3 = fmaf(e[13], w1, v3);
                v3 = fmaf(e[14], w2, v3); v3 = fmaf(e[15], w3, v3);
                v4 = fmaf(e[16], w0, v4); v4 = fmaf(e[17], w1, v4);
                v4 = fmaf(e[18], w2, v4); v4 = fmaf(e[19], w3, v4);
                v5 = fmaf(e[20], w0, v5); v5 = fmaf(e[21], w1, v5);
                v5 = fmaf(e[22], w2, v5); v5 = fmaf(e[23], w3, v5);
                v6 = fmaf(e[24], w0, v6); v6 = fmaf(e[25], w1, v6);
                v6 = fmaf(e[26], w2, v6); v6 = fmaf(e[27], w3, v6);
                v7 = fmaf(e[28], w0, v7); v7 = fmaf(e[29], w1, v7);
                v7 = fmaf(e[30], w2, v7); v7 = fmaf(e[31], w3, v7);
                const float s0 = (fmaxf(v0, 0.f) + fmaxf(v1, 0.f))
                               + (fmaxf(v2, 0.f) + fmaxf(v3, 0.f));
                const float s1 = (fmaxf(v4, 0.f) + fmaxf(v5, 0.f))
                               + (fmaxf(v6, 0.f) + fmaxf(v7, 0.f));
                hs[h] += s0 + s1;
            }
        }

        #pragma unroll
        for (int o = 0; o < ED; ++o) sp[o] = (float)NNB * cbp2n[o];
        #pragma unroll
        for (int h = 0; h < H1; ++h) {
            const float v = hs[h];
            #pragma unroll
            for (int o = 0; o < ED; ++o) sp[o] = fmaf(v, cWp2n[h * ED + o], sp[o]);
        }
    }
    // rho_n (hidden chunked by 16)
    #pragma unroll
    for (int o = 0; o < ED; ++o) rn[o] = cbr2n[o];
    #pragma unroll 1
    for (int c = 0; c < 4; ++c) {
        const int base = c * 16;
        float hc[16];
        #pragma unroll
        for (int h = 0; h < 16; ++h) hc[h] = cbr1n[base + h];
        #pragma unroll
        for (int i = 0; i < ED; ++i) {
            const float v = sp[i];
            #pragma unroll
            for (int h = 0; h < 16; ++h)
                hc[h] = fmaf(v, cWr1n[i * H1 + base + h], hc[h]);
        }
        #pragma unroll
        for (int h = 0; h < 16; ++h) {
            const float v = fmaxf(hc[h], 0.f);
            #pragma unroll
            for (int o = 0; o < ED; ++o)
                rn[o] = fmaf(v, cWr2n[(base + h) * ED + o], rn[o]);
        }
    }

    // ======================= obstacle deep-set =======================
    {
        float e[16];
        #pragma unroll
        for (int j = 0; j < 4; ++j) {
            const float4 v = xp[(size_t)(16 + j) * BMAX + t];
            e[4 * j + 0] = v.x; e[4 * j + 1] = v.y;
            e[4 * j + 2] = v.z; e[4 * j + 3] = v.w;
        }
        #pragma unroll
        for (int k = 0; k < 8; ++k)
            barrier_acc(e[2 * k + 0], e[2 * k + 1], 0.3f, bx, by);

        float hs[H1];
        #pragma unroll
        for (int h = 0; h < H1; ++h) {
            const float w0 = cWp1o[0 * H1 + h];
            const float w1 = cWp1o[1 * H1 + h];
            const float b  = cbp1o[h];
            float acc0 = 0.f, acc1 = 0.f;
            #pragma unroll
            for (int k = 0; k < 8; k += 2) {
                float va = b, vb = b;
                va = fmaf(e[2 * k + 0], w0, va);
                va = fmaf(e[2 * k + 1], w1, va);
                vb = fmaf(e[2 * k + 2], w0, vb);
                vb = fmaf(e[2 * k + 3], w1, vb);
                acc0 += fmaxf(va, 0.f);
                acc1 += fmaxf(vb, 0.f);
            }
            hs[h] = acc0 + acc1;
        }

        #pragma unroll
        for (int o = 0; o < ED; ++o) sp[o] = (float)NOB * cbp2o[o];
        #pragma unroll
        for (int h = 0; h < H1; ++h) {
            const float v = hs[h];
            #pragma unroll
            for (int o = 0; o < ED; ++o) sp[o] = fmaf(v, cWp2o[h * ED + o], sp[o]);
        }
    }
    #pragma unroll
    for (int o = 0; o < ED; ++o) ro[o] = cbr2o[o];
    #pragma unroll 1
    for (int c = 0; c < 4; ++c) {
        const int base = c * 16;
        float hc[16];
        #pragma unroll
        for (int h = 0; h < 16; ++h) hc[h] = cbr1o[base + h];
        #pragma unroll
        for (int i = 0; i < ED; ++i) {
            const float v = sp[i];
            #pragma unroll
            for (int h = 0; h < 16; ++h)
                hc[h] = fmaf(v, cWr1o[i * H1 + base + h], hc[h]);
        }
        #pragma unroll
        for (int h = 0; h < 16; ++h) {
            const float v = fmaxf(hc[h], 0.f);
            #pragma unroll
            for (int o = 0; o < ED; ++o)
                ro[o] = fmaf(v, cWr2o[(base + h) * ED + o], ro[o]);
        }
    }

    // ======================= psi head (chunked) =======================
    const float4 gv = xp[(size_t)20 * BMAX + t];
    const float g0 = gv.x, g1 = gv.y, g2 = gv.z, g3 = gv.w;
    float a0 = cbpsi2[0], a1 = cbpsi2[1];
    #pragma unroll 1
    for (int c = 0; c < 4; ++c) {
        const int base = c * 16;
        float hc[16];
        #pragma unroll
        for (int h = 0; h < 16; ++h) hc[h] = cbpsi1[base + h];
        #pragma unroll
        for (int i = 0; i < ED; ++i) {
            const float v = rn[i];
            #pragma unroll
            for (int h = 0; h < 16; ++h)
                hc[h] = fmaf(v, cWpsi1[i * HP + base + h], hc[h]);
        }
        #pragma unroll
        for (int i = 0; i < ED; ++i) {
            const float v = ro[i];
            #pragma unroll
            for (int h = 0; h < 16; ++h)
                hc[h] = fmaf(v, cWpsi1[(ED + i) * HP + base + h], hc[h]);
        }
        #pragma unroll
        for (int h = 0; h < 16; ++h) {
            float v = hc[h];
            v = fmaf(g0, cWpsi1[(2 * ED + 0) * HP + base + h], v);
            v = fmaf(g1, cWpsi1[(2 * ED + 1) * HP + base + h], v);
            v = fmaf(g2, cWpsi1[(2 * ED + 2) * HP + base + h], v);
            v = fmaf(g3, cWpsi1[(2 * ED + 3) * HP + base + h], v);
            v = fmaxf(v, 0.f);
            a0 = fmaf(v, cWpsi2[2 * (base + h) + 0], a0);
            a1 = fmaf(v, cWpsi2[2 * (base + h) + 1], a1);
        }
    }

    a0 = fmaf(2.0f, tanhf(a0), bx);
    a1 = fmaf(2.0f, tanhf(a1), by);

    const float inv = fmaxf(fmaxf(fabsf(a0), fabsf(a1)) * 0.5f, 1.0f);
    const float r   = __fdividef(1.0f, inv);
    float2 res;
    res.x = a0 * r;
    res.y = a1 * r;
    reinterpret_cast<float2*>(out)[t] = res;
}

extern "C" void kernel_launch(void* const* d_in, const int* in_sizes, int n_in,
                              void* d_out, int out_size) {
    const float* x = (const float*)d_in[0];
    float* out = (float*)d_out;
    const int nb = in_sizes[0] / XC;

    // async D2D copies of all weights into constant memory (graph-capturable)
    cudaMemcpyToSymbolAsync(cWp1n,  d_in[1],  SDIM * H1 * 4, 0, cudaMemcpyDeviceToDevice, 0);
    cudaMemcpyToSymbolAsync(cbp1n,  d_in[2],  H1 * 4,        0, cudaMemcpyDeviceToDevice, 0);
    cudaMemcpyToSymbolAsync(cWp2n,  d_in[3],  H1 * ED * 4,   0, cudaMemcpyDeviceToDevice, 0);
    cudaMemcpyToSymbolAsync(cbp2n,  d_in[4],  ED * 4,        0, cudaMemcpyDeviceToDevice, 0);
    cudaMemcpyToSymbolAsync(cWr1n,  d_in[5],  ED * H1 * 4,   0, cudaMemcpyDeviceToDevice, 0);
    cudaMemcpyToSymbolAsync(cbr1n,  d_in[6],  H1 * 4,        0, cudaMemcpyDeviceToDevice, 0);
    cudaMemcpyToSymbolAsync(cWr2n,  d_in[7],  H1 * ED * 4,   0, cudaMemcpyDeviceToDevice, 0);
    cudaMemcpyToSymbolAsync(cbr2n,  d_in[8],  ED * 4,        0, cudaMemcpyDeviceToDevice, 0);
    cudaMemcpyToSymbolAsync(cWp1o,  d_in[9],  2 * H1 * 4,    0, cudaMemcpyDeviceToDevice, 0);
    cudaMemcpyToSymbolAsync(cbp1o,  d_in[10], H1 * 4,        0, cudaMemcpyDeviceToDevice, 0);
    cudaMemcpyToSymbolAsync(cWp2o,  d_in[11], H1 * ED * 4,   0, cudaMemcpyDeviceToDevice, 0);
    cudaMemcpyToSymbolAsync(cbp2o,  d_in[12], ED * 4,        0, cudaMemcpyDeviceToDevice, 0);
    cudaMemcpyToSymbolAsync(cWr1o,  d_in[13], ED * H1 * 4,   0, cudaMemcpyDeviceToDevice, 0);
    cudaMemcpyToSymbolAsync(cbr1o,  d_in[14], H1 * 4,        0, cudaMemcpyDeviceToDevice, 0);
    cudaMemcpyToSymbolAsync(cWr2o,  d_in[15], H1 * ED * 4,   0, cudaMemcpyDeviceToDevice, 0);
    cudaMemcpyToSymbolAsync(cbr2o,  d_in[16], ED * 4,        0, cudaMemcpyDeviceToDevice, 0);
    cudaMemcpyToSymbolAsync(cWpsi1, d_in[17], (2 * ED + SDIM) * HP * 4, 0, cudaMemcpyDeviceToDevice, 0);
    cudaMemcpyToSymbolAsync(cbpsi1, d_in[18], HP * 4,        0, cudaMemcpyDeviceToDevice, 0);
    cudaMemcpyToSymbolAsync(cWpsi2, d_in[19], HP * 2 * 4,    0, cudaMemcpyDeviceToDevice, 0);
    cudaMemcpyToSymbolAsync(cbpsi2, d_in[20], 2 * 4,         0, cudaMemcpyDeviceToDevice, 0);

    pack_kernel<<<(nb + 31) / 32, 256>>>(x, nb);

    const int threads = 256;
    const int blocks = (nb + threads - 1) / threads;
    bnet_kernel<<<blocks, threads>>>(out, nb);
}

// round 11
// speedup vs baseline: 1.7254x; 1.0302x over previous
#include <cuda_runtime.h>
#include <math.h>

#define NNB  16
#define NOB  8
#define SDIM 4
#define H1   64
#define ED   16
#define HP   64
#define XC   85      // 1 + 4 + 64 + 16
#define BMAX 131072
#define NGRP 21      // 16 neighbor + 4 obstacle-pair + 1 goal group

// packed SoA scratch: g_xP[(grp*BMAX + b)*4 + c]
__device__ float g_xP[XC * BMAX];

// ---------------- all weights in constant memory (copied D2D at launch) ----------------
__constant__ float cWp1n[SDIM * H1];
__constant__ float cbp1n[H1];
__constant__ float cWp2n[H1 * ED];
__constant__ float cbp2n[ED];
__constant__ float cWr1n[ED * H1];
__constant__ float cbr1n[H1];
__constant__ float cWr2n[H1 * ED];
__constant__ float cbr2n[ED];
__constant__ float cWp1o[2 * H1];
__constant__ float cbp1o[H1];
__constant__ float cWp2o[H1 * ED];
__constant__ float cbp2o[ED];
__constant__ float cWr1o[ED * H1];
__constant__ float cbr1o[H1];
__constant__ float cWr2o[H1 * ED];
__constant__ float cbr2o[ED];
__constant__ float cWpsi1[(2 * ED + SDIM) * HP];
__constant__ float cbpsi1[HP];
__constant__ float cWpsi2[HP * 2];
__constant__ float cbpsi2[2];

// ---------------- pack kernel v2: vectorized staging ----------------
// x[B][85] -> float4 entity groups. Per-block slab is 16B-aligned
// (32*85*4 = 680 * 16), so stage with LDG.128/STS.128.
__global__ void __launch_bounds__(256)
pack_kernel(const float* __restrict__ x, int nb)
{
    __shared__ __align__(16) float buf[32 * 85];
    const int bBase = blockIdx.x * 32;

    if (bBase + 32 <= nb) {
        const float4* src = reinterpret_cast<const float4*>(x + (size_t)bBase * 85);
        float4* dst = reinterpret_cast<float4*>(buf);
        #pragma unroll 4
        for (int i = threadIdx.x; i < 680; i += 256)
            dst[i] = src[i];
    } else {
        for (int i = threadIdx.x; i < 32 * 85; i += 256) {
            const int r = i / 85, f = i - 85 * r;
            const int b = bBase + r;
            buf[i] = (b < nb) ? x[(size_t)b * 85 + f] : 0.f;
        }
    }
    __syncthreads();

    const int bl = threadIdx.x & 31;
    const int b  = bBase + bl;
    if (b < nb) {
        const float* row = buf + bl * 85;   // bank = (21*bl + f) % 32: conflict-free
        for (int g = threadIdx.x >> 5; g < NGRP; g += 8) {
            const int fb = (g < 16) ? (5 + 4 * g) : (g < 20 ? (69 + 4 * (g - 16)) : 1);
            float4 v;
            v.x = row[fb];     v.y = row[fb + 1];
            v.z = row[fb + 2]; v.w = row[fb + 3];
            *reinterpret_cast<float4*>(&g_xP[((size_t)g * BMAX + b) * 4]) = v;
        }
    }
}

__device__ __forceinline__ void barrier_acc(float e0, float e1, float D,
                                            float& bx, float& by) {
    const float px = -e0, py = -e1;
    const float q  = fmaf(px, px, py * py);
    const float rq = rsqrtf(q);
    const float nrm = q * rq;
    const float s  = 0.05f * __fdividef(1.0f, nrm * (nrm - D));
    bx = fmaf(s, px, bx);
    by = fmaf(s, py, by);
}

__global__ void __launch_bounds__(256, 2)
bnet_kernel(float* __restrict__ out, int nb)
{
    const int t = blockIdx.x * blockDim.x + threadIdx.x;
    if (t >= nb) return;

    const float4* xp = reinterpret_cast<const float4*>(g_xP);

    float bx = 0.f, by = 0.f;
    float rn[ED], ro[ED], sp[ED];

    // ======================= neighbor deep-set =======================
    {
        float hs[H1];
        #pragma unroll
        for (int h = 0; h < H1; ++h) hs[h] = 0.f;

        #pragma unroll 1
        for (int g = 0; g < 2; ++g) {
            float e[32];
            #pragma unroll
            for (int j = 0; j < 8; ++j) {
                const float4 v = xp[(size_t)(8 * g + j) * BMAX + t];
                e[4 * j + 0] = v.x; e[4 * j + 1] = v.y;
                e[4 * j + 2] = v.z; e[4 * j + 3] = v.w;
            }
            #pragma unroll
            for (int k = 0; k < 8; ++k)
                barrier_acc(e[4 * k + 0], e[4 * k + 1], 0.3f, bx, by);

            #pragma unroll
            for (int h = 0; h < H1; ++h) {
                const float w0 = cWp1n[0 * H1 + h];
                const float w1 = cWp1n[1 * H1 + h];
                const float w2 = cWp1n[2 * H1 + h];
                const float w3 = cWp1n[3 * H1 + h];
                const float b  = cbp1n[h];
                float v0 = b, v1 = b, v2 = b, v3 = b;
                float v4 = b, v5 = b, v6 = b, v7 = b;
                v0 = fmaf(e[0],  w0, v0); v0 = fmaf(e[1],  w1, v0);
                v0 = fmaf(e[2],  w2, v0); v0 = fmaf(e[3],  w3, v0);
                v1 = fmaf(e[4],  w0, v1); v1 = fmaf(e[5],  w1, v1);
                v1 = fmaf(e[6],  w2, v1); v1 = fmaf(e[7],  w3, v1);
                v2 = fmaf(e[8],  w0, v2); v2 = fmaf(e[9],  w1, v2);
                v2 = fmaf(e[10], w2, v2); v2 = fmaf(e[11], w3, v2);
                v3 = fmaf(e[12], w0, v3); v3 = fmaf(e[13], w1, v3);
                v3 = fmaf(e[14], w2, v3); v3 = fmaf(e[15], w3, v3);
                v4 = fmaf(e[16], w0, v4); v4 = fmaf(e[17], w1, v4);
                v4 = fmaf(e[18], w2, v4); v4 = fmaf(e[19], w3, v4);
                v5 = fmaf(e[20], w0, v5); v5 = fmaf(e[21], w1, v5);
                v5 = fmaf(e[22], w2, v5); v5 = fmaf(e[23], w3, v5);
                v6 = fmaf(e[24], w0, v6); v6 = fmaf(e[25], w1, v6);
                v6 = fmaf(e[26], w2, v6); v6 = fmaf(e[27], w3, v6);
                v7 = fmaf(e[28], w0, v7); v7 = fmaf(e[29], w1, v7);
                v7 = fmaf(e[30], w2, v7); v7 = fmaf(e[31], w3, v7);
                const float s0 = (fmaxf(v0, 0.f) + fmaxf(v1, 0.f))
                               + (fmaxf(v2, 0.f) + fmaxf(v3, 0.f));
                const float s1 = (fmaxf(v4, 0.f) + fmaxf(v5, 0.f))
                               + (fmaxf(v6, 0.f) + fmaxf(v7, 0.f));
                hs[h] += s0 + s1;
            }
        }

        #pragma unroll
        for (int o = 0; o < ED; ++o) sp[o] = (float)NNB * cbp2n[o];
        #pragma unroll
        for (int h = 0; h < H1; ++h) {
            const float v = hs[h];
            #pragma unroll
            for (int o = 0; o < ED; ++o) sp[o] = fmaf(v, cWp2n[h * ED + o], sp[o]);
        }
    }
    // rho_n (hidden chunked by 16)
    #pragma unroll
    for (int o = 0; o < ED; ++o) rn[o] = cbr2n[o];
    #pragma unroll 1
    for (int c = 0; c < 4; ++c) {
        const int base = c * 16;
        float hc[16];
        #pragma unroll
        for (int h = 0; h < 16; ++h) hc[h] = cbr1n[base + h];
        #pragma unroll
        for (int i = 0; i < ED; ++i) {
            const float v = sp[i];
            #pragma unroll
            for (int h = 0; h < 16; ++h)
                hc[h] = fmaf(v, cWr1n[i * H1 + base + h], hc[h]);
        }
        #pragma unroll
        for (int h = 0; h < 16; ++h) {
            const float v = fmaxf(hc[h], 0.f);
            #pragma unroll
            for (int o = 0; o < ED; ++o)
                rn[o] = fmaf(v, cWr2n[(base + h) * ED + o], rn[o]);
        }
    }

    // ======================= obstacle deep-set =======================
    {
        float e[16];
        #pragma unroll
        for (int j = 0; j < 4; ++j) {
            const float4 v = xp[(size_t)(16 + j) * BMAX + t];
            e[4 * j + 0] = v.x; e[4 * j + 1] = v.y;
            e[4 * j + 2] = v.z; e[4 * j + 3] = v.w;
        }
        #pragma unroll
        for (int k = 0; k < 8; ++k)
            barrier_acc(e[2 * k + 0], e[2 * k + 1], 0.3f, bx, by);

        float hs[H1];
        #pragma unroll
        for (int h = 0; h < H1; ++h) {
            const float w0 = cWp1o[0 * H1 + h];
            const float w1 = cWp1o[1 * H1 + h];
            const float b  = cbp1o[h];
            float acc0 = 0.f, acc1 = 0.f;
            #pragma unroll
            for (int k = 0; k < 8; k += 2) {
                float va = b, vb = b;
                va = fmaf(e[2 * k + 0], w0, va);
                va = fmaf(e[2 * k + 1], w1, va);
                vb = fmaf(e[2 * k + 2], w0, vb);
                vb = fmaf(e[2 * k + 3], w1, vb);
                acc0 += fmaxf(va, 0.f);
                acc1 += fmaxf(vb, 0.f);
            }
            hs[h] = acc0 + acc1;
        }

        #pragma unroll
        for (int o = 0; o < ED; ++o) sp[o] = (float)NOB * cbp2o[o];
        #pragma unroll
        for (int h = 0; h < H1; ++h) {
            const float v = hs[h];
            #pragma unroll
            for (int o = 0; o < ED; ++o) sp[o] = fmaf(v, cWp2o[h * ED + o], sp[o]);
        }
    }
    #pragma unroll
    for (int o = 0; o < ED; ++o) ro[o] = cbr2o[o];
    #pragma unroll 1
    for (int c = 0; c < 4; ++c) {
        const int base = c * 16;
        float hc[16];
        #pragma unroll
        for (int h = 0; h < 16; ++h) hc[h] = cbr1o[base + h];
        #pragma unroll
        for (int i = 0; i < ED; ++i) {
            const float v = sp[i];
            #pragma unroll
            for (int h = 0; h < 16; ++h)
                hc[h] = fmaf(v, cWr1o[i * H1 + base + h], hc[h]);
        }
        #pragma unroll
        for (int h = 0; h < 16; ++h) {
            const float v = fmaxf(hc[h], 0.f);
            #pragma unroll
            for (int o = 0; o < ED; ++o)
                ro[o] = fmaf(v, cWr2o[(base + h) * ED + o], ro[o]);
        }
    }

    // ======================= psi head (chunked) =======================
    const float4 gv = xp[(size_t)20 * BMAX + t];
    const float g0 = gv.x, g1 = gv.y, g2 = gv.z, g3 = gv.w;
    float a0 = cbpsi2[0], a1 = cbpsi2[1];
    #pragma unroll 1
    for (int c = 0; c < 4; ++c) {
        const int base = c * 16;
        float hc[16];
        #pragma unroll
        for (int h = 0; h < 16; ++h) hc[h] = cbpsi1[base + h];
        #pragma unroll
        for (int i = 0; i < ED; ++i) {
            const float v = rn[i];
            #pragma unroll
            for (int h = 0; h < 16; ++h)
                hc[h] = fmaf(v, cWpsi1[i * HP + base + h], hc[h]);
        }
        #pragma unroll
        for (int i = 0; i < ED; ++i) {
            const float v = ro[i];
            #pragma unroll
            for (int h = 0; h < 16; ++h)
                hc[h] = fmaf(v, cWpsi1[(ED + i) * HP + base + h], hc[h]);
        }
        #pragma unroll
        for (int h = 0; h < 16; ++h) {
            float v = hc[h];
            v = fmaf(g0, cWpsi1[(2 * ED + 0) * HP + base + h], v);
            v = fmaf(g1, cWpsi1[(2 * ED + 1) * HP + base + h], v);
            v = fmaf(g2, cWpsi1[(2 * ED + 2) * HP + base + h], v);
            v = fmaf(g3, cWpsi1[(2 * ED + 3) * HP + base + h], v);
            v = fmaxf(v, 0.f);
            a0 = fmaf(v, cWpsi2[2 * (base + h) + 0], a0);
            a1 = fmaf(v, cWpsi2[2 * (base + h) + 1], a1);
        }
    }

    a0 = fmaf(2.0f, tanhf(a0), bx);
    a1 = fmaf(2.0f, tanhf(a1), by);

    const float inv = fmaxf(fmaxf(fabsf(a0), fabsf(a1)) * 0.5f, 1.0f);
    const float r   = __fdividef(1.0f, inv);
    float2 res;
    res.x = a0 * r;
    res.y = a1 * r;
    reinterpret_cast<float2*>(out)[t] = res;
}

extern "C" void kernel_launch(void* const* d_in, const int* in_sizes, int n_in,
                              void* d_out, int out_size) {
    const float* x = (const float*)d_in[0];
    float* out = (float*)d_out;
    const int nb = in_sizes[0] / XC;

    // async D2D copies of all weights into constant memory (graph-capturable)
    cudaMemcpyToSymbolAsync(cWp1n,  d_in[1],  SDIM * H1 * 4, 0, cudaMemcpyDeviceToDevice, 0);
    cudaMemcpyToSymbolAsync(cbp1n,  d_in[2],  H1 * 4,        0, cudaMemcpyDeviceToDevice, 0);
    cudaMemcpyToSymbolAsync(cWp2n,  d_in[3],  H1 * ED * 4,   0, cudaMemcpyDeviceToDevice, 0);
    cudaMemcpyToSymbolAsync(cbp2n,  d_in[4],  ED * 4,        0, cudaMemcpyDeviceToDevice, 0);
    cudaMemcpyToSymbolAsync(cWr1n,  d_in[5],  ED * H1 * 4,   0, cudaMemcpyDeviceToDevice, 0);
    cudaMemcpyToSymbolAsync(cbr1n,  d_in[6],  H1 * 4,        0, cudaMemcpyDeviceToDevice, 0);
    cudaMemcpyToSymbolAsync(cWr2n,  d_in[7],  H1 * ED * 4,   0, cudaMemcpyDeviceToDevice, 0);
    cudaMemcpyToSymbolAsync(cbr2n,  d_in[8],  ED * 4,        0, cudaMemcpyDeviceToDevice, 0);
    cudaMemcpyToSymbolAsync(cWp1o,  d_in[9],  2 * H1 * 4,    0, cudaMemcpyDeviceToDevice, 0);
    cudaMemcpyToSymbolAsync(cbp1o,  d_in[10], H1 * 4,        0, cudaMemcpyDeviceToDevice, 0);
    cudaMemcpyToSymbolAsync(cWp2o,  d_in[11], H1 * ED * 4,   0, cudaMemcpyDeviceToDevice, 0);
    cudaMemcpyToSymbolAsync(cbp2o,  d_in[12], ED * 4,        0, cudaMemcpyDeviceToDevice, 0);
    cudaMemcpyToSymbolAsync(cWr1o,  d_in[13], ED * H1 * 4,   0, cudaMemcpyDeviceToDevice, 0);
    cudaMemcpyToSymbolAsync(cbr1o,  d_in[14], H1 * 4,        0, cudaMemcpyDeviceToDevice, 0);
    cudaMemcpyToSymbolAsync(cWr2o,  d_in[15], H1 * ED * 4,   0, cudaMemcpyDeviceToDevice, 0);
    cudaMemcpyToSymbolAsync(cbr2o,  d_in[16], ED * 4,        0, cudaMemcpyDeviceToDevice, 0);
    cudaMemcpyToSymbolAsync(cWpsi1, d_in[17], (2 * ED + SDIM) * HP * 4, 0, cudaMemcpyDeviceToDevice, 0);
    cudaMemcpyToSymbolAsync(cbpsi1, d_in[18], HP * 4,        0, cudaMemcpyDeviceToDevice, 0);
    cudaMemcpyToSymbolAsync(cWpsi2, d_in[19], HP * 2 * 4,    0, cudaMemcpyDeviceToDevice, 0);
    cudaMemcpyToSymbolAsync(cbpsi2, d_in[20], 2 * 4,         0, cudaMemcpyDeviceToDevice, 0);

    pack_kernel<<<(nb + 31) / 32, 256>>>(x, nb);

    const int threads = 256;
    const int blocks = (nb + threads - 1) / threads;
    bnet_kernel<<<blocks, threads>>>(out, nb);
}

// round 12
// speedup vs baseline: 1.8442x; 1.0688x over previous
#include <cuda_runtime.h>
#include <math.h>

#define NNB  16
#define NOB  8
#define SDIM 4
#define H1   64
#define ED   16
#define HP   64
#define XC   85      // 1 + 4 + 64 + 16
#define BMAX 131072
#define NGRP 21      // 16 neighbor + 4 obstacle-pair + 1 goal group

// packed SoA scratch: g_xP[(grp*BMAX + b)*4 + c]
__device__ float g_xP[XC * BMAX];

// ---------------- all weights in ONE constant blob ----------------
struct __align__(16) CW {
    float Wp1n_t[H1 * 4];   // [h][4]  (transposed)
    float bp1n[H1];
    float Wp2n[H1 * ED];
    float bp2n[ED];         // pre-scaled by NNB
    float Wr1n[ED * H1];
    float br1n[H1];
    float Wr2n[H1 * ED];
    float br2n[ED];
    float Wp1o_t[H1 * 2];   // [h][2]  (transposed)
    float bp1o[H1];
    float Wp2o[H1 * ED];
    float bp2o[ED];         // pre-scaled by NOB
    float Wr1o[ED * H1];
    float br1o[H1];
    float Wr2o[H1 * ED];
    float br2o[ED];
    float Wpsi1[(2 * ED + SDIM) * HP];
    float bpsi1[HP];
    float Wpsi2[HP * 2];
    float bpsi2[2];
    float pad[2];
};

__constant__ CW cw;
__device__ CW g_wblob;

struct WPtrs { const float* p[20]; };

#define LDC4(arr, off) (*reinterpret_cast<const float4*>(&(arr)[off]))
#define LDC2(arr, off) (*reinterpret_cast<const float2*>(&(arr)[off]))

// ---------------- gather kernel: pack weights into staging blob ----------------
__global__ void __launch_bounds__(256)
gather_kernel(WPtrs w)
{
    const int tid = threadIdx.x;
    // Wp1n transpose [4][64] -> [h][4]
    for (int i = tid; i < H1 * 4; i += 256) {
        int h = i >> 2, k = i & 3;
        g_wblob.Wp1n_t[i] = w.p[0][k * H1 + h];
    }
    // Wp1o transpose [2][64] -> [h][2]
    for (int i = tid; i < H1 * 2; i += 256) {
        int h = i >> 1, k = i & 1;
        g_wblob.Wp1o_t[i] = w.p[8][k * H1 + h];
    }
    for (int i = tid; i < ED; i += 256) {
        g_wblob.bp2n[i] = (float)NNB * w.p[3][i];
        g_wblob.bp2o[i] = (float)NOB * w.p[11][i];
    }
    {
        float* dsts[16] = { g_wblob.bp1n, g_wblob.Wp2n, g_wblob.Wr1n, g_wblob.br1n,
                            g_wblob.Wr2n, g_wblob.br2n,
                            g_wblob.bp1o, g_wblob.Wp2o, g_wblob.Wr1o, g_wblob.br1o,
                            g_wblob.Wr2o, g_wblob.br2o,
                            g_wblob.Wpsi1, g_wblob.bpsi1, g_wblob.Wpsi2, g_wblob.bpsi2 };
        const int srci[16] = { 1, 2, 4, 5, 6, 7, 9, 10, 12, 13, 14, 15, 16, 17, 18, 19 };
        const int ns[16]   = { H1, H1*ED, ED*H1, H1, H1*ED, ED,
                               H1, H1*ED, ED*H1, H1, H1*ED, ED,
                               (2*ED+SDIM)*HP, HP, HP*2, 2 };
        for (int a = 0; a < 16; ++a)
            for (int i = tid; i < ns[a]; i += 256)
                dsts[a][i] = w.p[srci[a]][i];
    }
}

// ---------------- pack kernel: x[B][85] -> float4 entity groups ----------------
__global__ void __launch_bounds__(256)
pack_kernel(const float* __restrict__ x, int nb)
{
    __shared__ __align__(16) float buf[32 * 85];
    const int bBase = blockIdx.x * 32;

    if (bBase + 32 <= nb) {
        const float4* src = reinterpret_cast<const float4*>(x + (size_t)bBase * 85);
        float4* dst = reinterpret_cast<float4*>(buf);
        #pragma unroll 4
        for (int i = threadIdx.x; i < 680; i += 256)
            dst[i] = src[i];
    } else {
        for (int i = threadIdx.x; i < 32 * 85; i += 256) {
            const int r = i / 85, f = i - 85 * r;
            const int b = bBase + r;
            buf[i] = (b < nb) ? x[(size_t)b * 85 + f] : 0.f;
        }
    }
    __syncthreads();

    const int bl = threadIdx.x & 31;
    const int b  = bBase + bl;
    if (b < nb) {
        const float* row = buf + bl * 85;
        for (int g = threadIdx.x >> 5; g < NGRP; g += 8) {
            const int fb = (g < 16) ? (5 + 4 * g) : (g < 20 ? (69 + 4 * (g - 16)) : 1);
            float4 v;
            v.x = row[fb];     v.y = row[fb + 1];
            v.z = row[fb + 2]; v.w = row[fb + 3];
            *reinterpret_cast<float4*>(&g_xP[((size_t)g * BMAX + b) * 4]) = v;
        }
    }
}

__device__ __forceinline__ void barrier_acc(float e0, float e1, float D,
                                            float& bx, float& by) {
    const float px = -e0, py = -e1;
    const float q  = fmaf(px, px, py * py);
    const float rq = rsqrtf(q);
    const float nrm = q * rq;
    const float s  = 0.05f * __fdividef(1.0f, nrm * (nrm - D));
    bx = fmaf(s, px, bx);
    by = fmaf(s, py, by);
}

__global__ void __launch_bounds__(256, 2)
bnet_kernel(float* __restrict__ out, int nb)
{
    const int t = blockIdx.x * blockDim.x + threadIdx.x;
    if (t >= nb) return;

    const float4* xp = reinterpret_cast<const float4*>(g_xP);

    float bx = 0.f, by = 0.f;
    float rn[ED], ro[ED], sp[ED];

    // ======================= neighbor deep-set =======================
    {
        float hs[H1];
        #pragma unroll
        for (int h = 0; h < H1; ++h) hs[h] = 0.f;

        #pragma unroll 1
        for (int g = 0; g < 2; ++g) {
            float e[32];
            #pragma unroll
            for (int j = 0; j < 8; ++j) {
                const float4 v = xp[(size_t)(8 * g + j) * BMAX + t];
                e[4 * j + 0] = v.x; e[4 * j + 1] = v.y;
                e[4 * j + 2] = v.z; e[4 * j + 3] = v.w;
            }
            #pragma unroll
            for (int k = 0; k < 8; ++k)
                barrier_acc(e[4 * k + 0], e[4 * k + 1], 0.3f, bx, by);

            #pragma unroll
            for (int h = 0; h < H1; ++h) {
                const float4 w = LDC4(cw.Wp1n_t, h * 4);
                const float b  = cw.bp1n[h];
                float v0 = b, v1 = b, v2 = b, v3 = b;
                float v4 = b, v5 = b, v6 = b, v7 = b;
                v0 = fmaf(e[0],  w.x, v0); v0 = fmaf(e[1],  w.y, v0);
                v0 = fmaf(e[2],  w.z, v0); v0 = fmaf(e[3],  w.w, v0);
                v1 = fmaf(e[4],  w.x, v1); v1 = fmaf(e[5],  w.y, v1);
                v1 = fmaf(e[6],  w.z, v1); v1 = fmaf(e[7],  w.w, v1);
                v2 = fmaf(e[8],  w.x, v2); v2 = fmaf(e[9],  w.y, v2);
                v2 = fmaf(e[10], w.z, v2); v2 = fmaf(e[11], w.w, v2);
                v3 = fmaf(e[12], w.x, v3); v3 = fmaf(e[13], w.y, v3);
                v3 = fmaf(e[14], w.z, v3); v3 = fmaf(e[15], w.w, v3);
                v4 = fmaf(e[16], w.x, v4); v4 = fmaf(e[17], w.y, v4);
                v4 = fmaf(e[18], w.z, v4); v4 = fmaf(e[19], w.w, v4);
                v5 = fmaf(e[20], w.x, v5); v5 = fmaf(e[21], w.y, v5);
                v5 = fmaf(e[22], w.z, v5); v5 = fmaf(e[23], w.w, v5);
                v6 = fmaf(e[24], w.x, v6); v6 = fmaf(e[25], w.y, v6);
                v6 = fmaf(e[26], w.z, v6); v6 = fmaf(e[27], w.w, v6);
                v7 = fmaf(e[28], w.x, v7); v7 = fmaf(e[29], w.y, v7);
                v7 = fmaf(e[30], w.z, v7); v7 = fmaf(e[31], w.w, v7);
                const float s0 = (fmaxf(v0, 0.f) + fmaxf(v1, 0.f))
                               + (fmaxf(v2, 0.f) + fmaxf(v3, 0.f));
                const float s1 = (fmaxf(v4, 0.f) + fmaxf(v5, 0.f))
                               + (fmaxf(v6, 0.f) + fmaxf(v7, 0.f));
                hs[h] += s0 + s1;
            }
        }

        // sp = hs @ Wp2n + NNB*bp2n  (vectorized weights)
        #pragma unroll
        for (int j = 0; j < 4; ++j) {
            const float4 b = LDC4(cw.bp2n, 4 * j);
            sp[4*j+0] = b.x; sp[4*j+1] = b.y; sp[4*j+2] = b.z; sp[4*j+3] = b.w;
        }
        #pragma unroll
        for (int h = 0; h < H1; ++h) {
            const float v = hs[h];
            #pragma unroll
            for (int j = 0; j < 4; ++j) {
                const float4 w = LDC4(cw.Wp2n, h * ED + 4 * j);
                sp[4*j+0] = fmaf(v, w.x, sp[4*j+0]);
                sp[4*j+1] = fmaf(v, w.y, sp[4*j+1]);
                sp[4*j+2] = fmaf(v, w.z, sp[4*j+2]);
                sp[4*j+3] = fmaf(v, w.w, sp[4*j+3]);
            }
        }
    }
    // rho_n (hidden chunked by 16, vectorized weights)
    #pragma unroll
    for (int j = 0; j < 4; ++j) {
        const float4 b = LDC4(cw.br2n, 4 * j);
        rn[4*j+0] = b.x; rn[4*j+1] = b.y; rn[4*j+2] = b.z; rn[4*j+3] = b.w;
    }
    #pragma unroll 1
    for (int c = 0; c < 4; ++c) {
        const int base = c * 16;
        float hc[16];
        #pragma unroll
        for (int q = 0; q < 4; ++q) {
            const float4 b = LDC4(cw.br1n, base + 4 * q);
            hc[4*q+0] = b.x; hc[4*q+1] = b.y; hc[4*q+2] = b.z; hc[4*q+3] = b.w;
        }
        #pragma unroll
        for (int i = 0; i < ED; ++i) {
            const float v = sp[i];
            #pragma unroll
            for (int j = 0; j < 4; ++j) {
                const float4 w = LDC4(cw.Wr1n, i * H1 + base + 4 * j);
                hc[4*j+0] = fmaf(v, w.x, hc[4*j+0]);
                hc[4*j+1] = fmaf(v, w.y, hc[4*j+1]);
                hc[4*j+2] = fmaf(v, w.z, hc[4*j+2]);
                hc[4*j+3] = fmaf(v, w.w, hc[4*j+3]);
            }
        }
        #pragma unroll
        for (int h = 0; h < 16; ++h) {
            const float v = fmaxf(hc[h], 0.f);
            #pragma unroll
            for (int j = 0; j < 4; ++j) {
                const float4 w = LDC4(cw.Wr2n, (base + h) * ED + 4 * j);
                rn[4*j+0] = fmaf(v, w.x, rn[4*j+0]);
                rn[4*j+1] = fmaf(v, w.y, rn[4*j+1]);
                rn[4*j+2] = fmaf(v, w.z, rn[4*j+2]);
                rn[4*j+3] = fmaf(v, w.w, rn[4*j+3]);
            }
        }
    }

    // ======================= obstacle deep-set =======================
    {
        float e[16];
        #pragma unroll
        for (int j = 0; j < 4; ++j) {
            const float4 v = xp[(size_t)(16 + j) * BMAX + t];
            e[4 * j + 0] = v.x; e[4 * j + 1] = v.y;
            e[4 * j + 2] = v.z; e[4 * j + 3] = v.w;
        }
        #pragma unroll
        for (int k = 0; k < 8; ++k)
            barrier_acc(e[2 * k + 0], e[2 * k + 1], 0.3f, bx, by);

        float hs[H1];
        #pragma unroll
        for (int h = 0; h < H1; ++h) {
            const float2 w = LDC2(cw.Wp1o_t, h * 2);
            const float b  = cw.bp1o[h];
            float acc0 = 0.f, acc1 = 0.f;
            #pragma unroll
            for (int k = 0; k < 8; k += 2) {
                float va = b, vb = b;
                va = fmaf(e[2 * k + 0], w.x, va);
                va = fmaf(e[2 * k + 1], w.y, va);
                vb = fmaf(e[2 * k + 2], w.x, vb);
                vb = fmaf(e[2 * k + 3], w.y, vb);
                acc0 += fmaxf(va, 0.f);
                acc1 += fmaxf(vb, 0.f);
            }
            hs[h] = acc0 + acc1;
        }

        #pragma unroll
        for (int j = 0; j < 4; ++j) {
            const float4 b = LDC4(cw.bp2o, 4 * j);
            sp[4*j+0] = b.x; sp[4*j+1] = b.y; sp[4*j+2] = b.z; sp[4*j+3] = b.w;
        }
        #pragma unroll
        for (int h = 0; h < H1; ++h) {
            const float v = hs[h];
            #pragma unroll
            for (int j = 0; j < 4; ++j) {
                const float4 w = LDC4(cw.Wp2o, h * ED + 4 * j);
                sp[4*j+0] = fmaf(v, w.x, sp[4*j+0]);
                sp[4*j+1] = fmaf(v, w.y, sp[4*j+1]);
                sp[4*j+2] = fmaf(v, w.z, sp[4*j+2]);
                sp[4*j+3] = fmaf(v, w.w, sp[4*j+3]);
            }
        }
    }
    #pragma unroll
    for (int j = 0; j < 4; ++j) {
        const float4 b = LDC4(cw.br2o, 4 * j);
        ro[4*j+0] = b.x; ro[4*j+1] = b.y; ro[4*j+2] = b.z; ro[4*j+3] = b.w;
    }
    #pragma unroll 1
    for (int c = 0; c < 4; ++c) {
        const int base = c * 16;
        float hc[16];
        #pragma unroll
        for (int q = 0; q < 4; ++q) {
            const float4 b = LDC4(cw.br1o, base + 4 * q);
            hc[4*q+0] = b.x; hc[4*q+1] = b.y; hc[4*q+2] = b.z; hc[4*q+3] = b.w;
        }
        #pragma unroll
        for (int i = 0; i < ED; ++i) {
            const float v = sp[i];
            #pragma unroll
            for (int j = 0; j < 4; ++j) {
                const float4 w = LDC4(cw.Wr1o, i * H1 + base + 4 * j);
                hc[4*j+0] = fmaf(v, w.x, hc[4*j+0]);
                hc[4*j+1] = fmaf(v, w.y, hc[4*j+1]);
                hc[4*j+2] = fmaf(v, w.z, hc[4*j+2]);
                hc[4*j+3] = fmaf(v, w.w, hc[4*j+3]);
            }
        }
        #pragma unroll
        for (int h = 0; h < 16; ++h) {
            const float v = fmaxf(hc[h], 0.f);
            #pragma unroll
            for (int j = 0; j < 4; ++j) {
                const float4 w = LDC4(cw.Wr2o, (base + h) * ED + 4 * j);
                ro[4*j+0] = fmaf(v, w.x, ro[4*j+0]);
                ro[4*j+1] = fmaf(v, w.y, ro[4*j+1]);
                ro[4*j+2] = fmaf(v, w.z, ro[4*j+2]);
                ro[4*j+3] = fmaf(v, w.w, ro[4*j+3]);
            }
        }
    }

    // ======================= psi head (chunked, vectorized) =======================
    const float4 gv = xp[(size_t)20 * BMAX + t];
    const float gs[4] = { gv.x, gv.y, gv.z, gv.w };
    float a0 = cw.bpsi2[0], a1 = cw.bpsi2[1];
    #pragma unroll 1
    for (int c = 0; c < 4; ++c) {
        const int base = c * 16;
        float hc[16];
        #pragma unroll
        for (int q = 0; q < 4; ++q) {
            const float4 b = LDC4(cw.bpsi1, base + 4 * q);
            hc[4*q+0] = b.x; hc[4*q+1] = b.y; hc[4*q+2] = b.z; hc[4*q+3] = b.w;
        }
        #pragma unroll
        for (int i = 0; i < ED; ++i) {
            const float v = rn[i];
            #pragma unroll
            for (int j = 0; j < 4; ++j) {
                const float4 w = LDC4(cw.Wpsi1, i * HP + base + 4 * j);
                hc[4*j+0] = fmaf(v, w.x, hc[4*j+0]);
                hc[4*j+1] = fmaf(v, w.y, hc[4*j+1]);
                hc[4*j+2] = fmaf(v, w.z, hc[4*j+2]);
                hc[4*j+3] = fmaf(v, w.w, hc[4*j+3]);
            }
        }
        #pragma unroll
        for (int i = 0; i < ED; ++i) {
            const float v = ro[i];
            #pragma unroll
            for (int j = 0; j < 4; ++j) {
                const float4 w = LDC4(cw.Wpsi1, (ED + i) * HP + base + 4 * j);
                hc[4*j+0] = fmaf(v, w.x, hc[4*j+0]);
                hc[4*j+1] = fmaf(v, w.y, hc[4*j+1]);
                hc[4*j+2] = fmaf(v, w.z, hc[4*j+2]);
                hc[4*j+3] = fmaf(v, w.w, hc[4*j+3]);
            }
        }
        #pragma unroll
        for (int k = 0; k < 4; ++k) {
            const float v = gs[k];
            #pragma unroll
            for (int j = 0; j < 4; ++j) {
                const float4 w = LDC4(cw.Wpsi1, (2 * ED + k) * HP + base + 4 * j);
                hc[4*j+0] = fmaf(v, w.x, hc[4*j+0]);
                hc[4*j+1] = fmaf(v, w.y, hc[4*j+1]);
                hc[4*j+2] = fmaf(v, w.z, hc[4*j+2]);
                hc[4*j+3] = fmaf(v, w.w, hc[4*j+3]);
            }
        }
        #pragma unroll
        for (int h = 0; h < 16; h += 2) {
            const float v0 = fmaxf(hc[h], 0.f);
            const float v1 = fmaxf(hc[h + 1], 0.f);
            const float4 w = LDC4(cw.Wpsi2, 2 * (base + h));
            a0 = fmaf(v0, w.x, a0); a1 = fmaf(v0, w.y, a1);
            a0 = fmaf(v1, w.z, a0); a1 = fmaf(v1, w.w, a1);
        }
    }

    a0 = fmaf(2.0f, tanhf(a0), bx);
    a1 = fmaf(2.0f, tanhf(a1), by);

    const float inv = fmaxf(fmaxf(fabsf(a0), fabsf(a1)) * 0.5f, 1.0f);
    const float r   = __fdividef(1.0f, inv);
    float2 res;
    res.x = a0 * r;
    res.y = a1 * r;
    reinterpret_cast<float2*>(out)[t] = res;
}

extern "C" void kernel_launch(void* const* d_in, const int* in_sizes, int n_in,
                              void* d_out, int out_size) {
    const float* x = (const float*)d_in[0];
    float* out = (float*)d_out;
    const int nb = in_sizes[0] / XC;

    WPtrs w;
    for (int i = 0; i < 20; ++i) w.p[i] = (const float*)d_in[i + 1];

    gather_kernel<<<1, 256>>>(w);

    void* blobAddr = nullptr;
    cudaGetSymbolAddress(&blobAddr, g_wblob);
    cudaMemcpyToSymbolAsync(cw, blobAddr, sizeof(CW), 0, cudaMemcpyDeviceToDevice, 0);

    pack_kernel<<<(nb + 31) / 32, 256>>>(x, nb);

    const int threads = 256;
    const int blocks = (nb + threads - 1) / threads;
    bnet_kernel<<<blocks, threads>>>(out, nb);
}

// round 13
// speedup vs baseline: 2.0738x; 1.1245x over previous
#include <cuda_runtime.h>
#include <math.h>

#define NNB  16
#define NOB  8
#define SDIM 4
#define H1   64
#define ED   16
#define HP   64
#define XC   85      // 1 + 4 + 64 + 16
#define BMAX 131072
#define NGRP 21      // 16 neighbor + 4 obstacle-pair + 1 goal group

// packed SoA scratch: g_xP[(grp*BMAX + b)*4 + c]
__device__ float g_xP[XC * BMAX];

// ---------------- all weights in ONE constant blob ----------------
struct __align__(16) CW {
    float Wp1n_t[H1 * 4];   // [h][4]  (transposed)
    float bp1n[H1];
    float Wp2n[H1 * ED];
    float bp2n[ED];         // pre-scaled by NNB
    float Wr1n[ED * H1];
    float br1n[H1];
    float Wr2n[H1 * ED];
    float br2n[ED];
    float Wp1o_t[H1 * 2];   // [h][2]  (transposed)
    float bp1o[H1];
    float Wp2o[H1 * ED];
    float bp2o[ED];         // pre-scaled by NOB
    float Wr1o[ED * H1];
    float br1o[H1];
    float Wr2o[H1 * ED];
    float br2o[ED];
    float Wpsi1[(2 * ED + SDIM) * HP];
    float bpsi1[HP];
    float Wpsi2[HP * 2];
    float bpsi2[2];
    float pad[2];
};

__constant__ CW cw;
__device__ CW g_wblob;

struct WPtrs { const float* p[20]; };

#define LDC4(arr, off) (*reinterpret_cast<const float4*>(&(arr)[off]))
#define LDC2(arr, off) (*reinterpret_cast<const float2*>(&(arr)[off]))

// ---------------- prep kernel: pack x AND gather weights in one launch ----------------
// blocks [0, nbBlocks): pack x[B][85] -> float4 entity groups
// blocks [nbBlocks, nbBlocks+18): one weight tensor each (parallel gather)
__global__ void __launch_bounds__(256)
prep_kernel(const float* __restrict__ x, int nb, int nbBlocks, WPtrs w)
{
    if (blockIdx.x >= (unsigned)nbBlocks) {
        const int a = blockIdx.x - nbBlocks;   // 0..17
        const int tid = threadIdx.x;
        if (a == 16) {                 // Wp1n transpose [4][64] -> [h][4]
            for (int i = tid; i < H1 * 4; i += 256) {
                int h = i >> 2, k = i & 3;
                g_wblob.Wp1n_t[i] = w.p[0][k * H1 + h];
            }
        } else if (a == 17) {          // Wp1o transpose + pre-scaled bp2n/bp2o
            for (int i = tid; i < H1 * 2; i += 256) {
                int h = i >> 1, k = i & 1;
                g_wblob.Wp1o_t[i] = w.p[8][k * H1 + h];
            }
            for (int i = tid; i < ED; i += 256) {
                g_wblob.bp2n[i] = (float)NNB * w.p[3][i];
                g_wblob.bp2o[i] = (float)NOB * w.p[11][i];
            }
        } else {
            float* dsts[16] = { g_wblob.bp1n, g_wblob.Wp2n, g_wblob.Wr1n, g_wblob.br1n,
                                g_wblob.Wr2n, g_wblob.br2n,
                                g_wblob.bp1o, g_wblob.Wp2o, g_wblob.Wr1o, g_wblob.br1o,
                                g_wblob.Wr2o, g_wblob.br2o,
                                g_wblob.Wpsi1, g_wblob.bpsi1, g_wblob.Wpsi2, g_wblob.bpsi2 };
            const int srci[16] = { 1, 2, 4, 5, 6, 7, 9, 10, 12, 13, 14, 15, 16, 17, 18, 19 };
            const int ns[16]   = { H1, H1*ED, ED*H1, H1, H1*ED, ED,
                                   H1, H1*ED, ED*H1, H1, H1*ED, ED,
                                   (2*ED+SDIM)*HP, HP, HP*2, 2 };
            float* dst = dsts[a];
            const float* src = w.p[srci[a]];
            const int n = ns[a];
            for (int i = tid; i < n; i += 256)
                dst[i] = src[i];
        }
        return;
    }

    // ---- x packing ----
    __shared__ __align__(16) float buf[32 * 85];
    const int bBase = blockIdx.x * 32;

    if (bBase + 32 <= nb) {
        const float4* src = reinterpret_cast<const float4*>(x + (size_t)bBase * 85);
        float4* dst = reinterpret_cast<float4*>(buf);
        #pragma unroll 4
        for (int i = threadIdx.x; i < 680; i += 256)
            dst[i] = src[i];
    } else {
        for (int i = threadIdx.x; i < 32 * 85; i += 256) {
            const int r = i / 85, f = i - 85 * r;
            const int b = bBase + r;
            buf[i] = (b < nb) ? x[(size_t)b * 85 + f] : 0.f;
        }
    }
    __syncthreads();

    const int bl = threadIdx.x & 31;
    const int b  = bBase + bl;
    if (b < nb) {
        const float* row = buf + bl * 85;
        for (int g = threadIdx.x >> 5; g < NGRP; g += 8) {
            const int fb = (g < 16) ? (5 + 4 * g) : (g < 20 ? (69 + 4 * (g - 16)) : 1);
            float4 v;
            v.x = row[fb];     v.y = row[fb + 1];
            v.z = row[fb + 2]; v.w = row[fb + 3];
            *reinterpret_cast<float4*>(&g_xP[((size_t)g * BMAX + b) * 4]) = v;
        }
    }
}

__device__ __forceinline__ void barrier_acc(float e0, float e1, float D,
                                            float& bx, float& by) {
    const float px = -e0, py = -e1;
    const float q  = fmaf(px, px, py * py);
    const float rq = rsqrtf(q);
    const float nrm = q * rq;
    const float s  = 0.05f * __fdividef(1.0f, nrm * (nrm - D));
    bx = fmaf(s, px, bx);
    by = fmaf(s, py, by);
}

__global__ void __launch_bounds__(256, 2)
bnet_kernel(float* __restrict__ out, int nb)
{
    const int t = blockIdx.x * blockDim.x + threadIdx.x;
    if (t >= nb) return;

    const float4* xp = reinterpret_cast<const float4*>(g_xP);

    float bx = 0.f, by = 0.f;
    float rn[ED], ro[ED], sp[ED];

    // ======================= neighbor deep-set =======================
    {
        float hs[H1];
        #pragma unroll
        for (int h = 0; h < H1; ++h) hs[h] = 0.f;

        #pragma unroll 1
        for (int g = 0; g < 2; ++g) {
            float e[32];
            #pragma unroll
            for (int j = 0; j < 8; ++j) {
                const float4 v = xp[(size_t)(8 * g + j) * BMAX + t];
                e[4 * j + 0] = v.x; e[4 * j + 1] = v.y;
                e[4 * j + 2] = v.z; e[4 * j + 3] = v.w;
            }
            #pragma unroll
            for (int k = 0; k < 8; ++k)
                barrier_acc(e[4 * k + 0], e[4 * k + 1], 0.3f, bx, by);

            #pragma unroll
            for (int h = 0; h < H1; ++h) {
                const float4 w = LDC4(cw.Wp1n_t, h * 4);
                const float b  = cw.bp1n[h];
                float v0 = b, v1 = b, v2 = b, v3 = b;
                float v4 = b, v5 = b, v6 = b, v7 = b;
                v0 = fmaf(e[0],  w.x, v0); v0 = fmaf(e[1],  w.y, v0);
                v0 = fmaf(e[2],  w.z, v0); v0 = fmaf(e[3],  w.w, v0);
                v1 = fmaf(e[4],  w.x, v1); v1 = fmaf(e[5],  w.y, v1);
                v1 = fmaf(e[6],  w.z, v1); v1 = fmaf(e[7],  w.w, v1);
                v2 = fmaf(e[8],  w.x, v2); v2 = fmaf(e[9],  w.y, v2);
                v2 = fmaf(e[10], w.z, v2); v2 = fmaf(e[11], w.w, v2);
                v3 = fmaf(e[12], w.x, v3); v3 = fmaf(e[13], w.y, v3);
                v3 = fmaf(e[14], w.z, v3); v3 = fmaf(e[15], w.w, v3);
                v4 = fmaf(e[16], w.x, v4); v4 = fmaf(e[17], w.y, v4);
                v4 = fmaf(e[18], w.z, v4); v4 = fmaf(e[19], w.w, v4);
                v5 = fmaf(e[20], w.x, v5); v5 = fmaf(e[21], w.y, v5);
                v5 = fmaf(e[22], w.z, v5); v5 = fmaf(e[23], w.w, v5);
                v6 = fmaf(e[24], w.x, v6); v6 = fmaf(e[25], w.y, v6);
                v6 = fmaf(e[26], w.z, v6); v6 = fmaf(e[27], w.w, v6);
                v7 = fmaf(e[28], w.x, v7); v7 = fmaf(e[29], w.y, v7);
                v7 = fmaf(e[30], w.z, v7); v7 = fmaf(e[31], w.w, v7);
                const float s0 = (fmaxf(v0, 0.f) + fmaxf(v1, 0.f))
                               + (fmaxf(v2, 0.f) + fmaxf(v3, 0.f));
                const float s1 = (fmaxf(v4, 0.f) + fmaxf(v5, 0.f))
                               + (fmaxf(v6, 0.f) + fmaxf(v7, 0.f));
                hs[h] += s0 + s1;
            }
        }

        #pragma unroll
        for (int j = 0; j < 4; ++j) {
            const float4 b = LDC4(cw.bp2n, 4 * j);
            sp[4*j+0] = b.x; sp[4*j+1] = b.y; sp[4*j+2] = b.z; sp[4*j+3] = b.w;
        }
        #pragma unroll
        for (int h = 0; h < H1; ++h) {
            const float v = hs[h];
            #pragma unroll
            for (int j = 0; j < 4; ++j) {
                const float4 w = LDC4(cw.Wp2n, h * ED + 4 * j);
                sp[4*j+0] = fmaf(v, w.x, sp[4*j+0]);
                sp[4*j+1] = fmaf(v, w.y, sp[4*j+1]);
                sp[4*j+2] = fmaf(v, w.z, sp[4*j+2]);
                sp[4*j+3] = fmaf(v, w.w, sp[4*j+3]);
            }
        }
    }
    // rho_n
    #pragma unroll
    for (int j = 0; j < 4; ++j) {
        const float4 b = LDC4(cw.br2n, 4 * j);
        rn[4*j+0] = b.x; rn[4*j+1] = b.y; rn[4*j+2] = b.z; rn[4*j+3] = b.w;
    }
    #pragma unroll 1
    for (int c = 0; c < 4; ++c) {
        const int base = c * 16;
        float hc[16];
        #pragma unroll
        for (int q = 0; q < 4; ++q) {
            const float4 b = LDC4(cw.br1n, base + 4 * q);
            hc[4*q+0] = b.x; hc[4*q+1] = b.y; hc[4*q+2] = b.z; hc[4*q+3] = b.w;
        }
        #pragma unroll
        for (int i = 0; i < ED; ++i) {
            const float v = sp[i];
            #pragma unroll
            for (int j = 0; j < 4; ++j) {
                const float4 w = LDC4(cw.Wr1n, i * H1 + base + 4 * j);
                hc[4*j+0] = fmaf(v, w.x, hc[4*j+0]);
                hc[4*j+1] = fmaf(v, w.y, hc[4*j+1]);
                hc[4*j+2] = fmaf(v, w.z, hc[4*j+2]);
                hc[4*j+3] = fmaf(v, w.w, hc[4*j+3]);
            }
        }
        #pragma unroll
        for (int h = 0; h < 16; ++h) {
            const float v = fmaxf(hc[h], 0.f);
            #pragma unroll
            for (int j = 0; j < 4; ++j) {
                const float4 w = LDC4(cw.Wr2n, (base + h) * ED + 4 * j);
                rn[4*j+0] = fmaf(v, w.x, rn[4*j+0]);
                rn[4*j+1] = fmaf(v, w.y, rn[4*j+1]);
                rn[4*j+2] = fmaf(v, w.z, rn[4*j+2]);
                rn[4*j+3] = fmaf(v, w.w, rn[4*j+3]);
            }
        }
    }

    // ======================= obstacle deep-set =======================
    {
        float e[16];
        #pragma unroll
        for (int j = 0; j < 4; ++j) {
            const float4 v = xp[(size_t)(16 + j) * BMAX + t];
            e[4 * j + 0] = v.x; e[4 * j + 1] = v.y;
            e[4 * j + 2] = v.z; e[4 * j + 3] = v.w;
        }
        #pragma unroll
        for (int k = 0; k < 8; ++k)
            barrier_acc(e[2 * k + 0], e[2 * k + 1], 0.3f, bx, by);

        float hs[H1];
        #pragma unroll
        for (int h = 0; h < H1; ++h) {
            const float2 w = LDC2(cw.Wp1o_t, h * 2);
            const float b  = cw.bp1o[h];
            float acc0 = 0.f, acc1 = 0.f;
            #pragma unroll
            for (int k = 0; k < 8; k += 2) {
                float va = b, vb = b;
                va = fmaf(e[2 * k + 0], w.x, va);
                va = fmaf(e[2 * k + 1], w.y, va);
                vb = fmaf(e[2 * k + 2], w.x, vb);
                vb = fmaf(e[2 * k + 3], w.y, vb);
                acc0 += fmaxf(va, 0.f);
                acc1 += fmaxf(vb, 0.f);
            }
            hs[h] = acc0 + acc1;
        }

        #pragma unroll
        for (int j = 0; j < 4; ++j) {
            const float4 b = LDC4(cw.bp2o, 4 * j);
            sp[4*j+0] = b.x; sp[4*j+1] = b.y; sp[4*j+2] = b.z; sp[4*j+3] = b.w;
        }
        #pragma unroll
        for (int h = 0; h < H1; ++h) {
            const float v = hs[h];
            #pragma unroll
            for (int j = 0; j < 4; ++j) {
                const float4 w = LDC4(cw.Wp2o, h * ED + 4 * j);
                sp[4*j+0] = fmaf(v, w.x, sp[4*j+0]);
                sp[4*j+1] = fmaf(v, w.y, sp[4*j+1]);
                sp[4*j+2] = fmaf(v, w.z, sp[4*j+2]);
                sp[4*j+3] = fmaf(v, w.w, sp[4*j+3]);
            }
        }
    }
    #pragma unroll
    for (int j = 0; j < 4; ++j) {
        const float4 b = LDC4(cw.br2o, 4 * j);
        ro[4*j+0] = b.x; ro[4*j+1] = b.y; ro[4*j+2] = b.z; ro[4*j+3] = b.w;
    }
    #pragma unroll 1
    for (int c = 0; c < 4; ++c) {
        const int base = c * 16;
        float hc[16];
        #pragma unroll
        for (int q = 0; q < 4; ++q) {
            const float4 b = LDC4(cw.br1o, base + 4 * q);
            hc[4*q+0] = b.x; hc[4*q+1] = b.y; hc[4*q+2] = b.z; hc[4*q+3] = b.w;
        }
        #pragma unroll
        for (int i = 0; i < ED; ++i) {
            const float v = sp[i];
            #pragma unroll
            for (int j = 0; j < 4; ++j) {
                const float4 w = LDC4(cw.Wr1o, i * H1 + base + 4 * j);
                hc[4*j+0] = fmaf(v, w.x, hc[4*j+0]);
                hc[4*j+1] = fmaf(v, w.y, hc[4*j+1]);
                hc[4*j+2] = fmaf(v, w.z, hc[4*j+2]);
                hc[4*j+3] = fmaf(v, w.w, hc[4*j+3]);
            }
        }
        #pragma unroll
        for (int h = 0; h < 16; ++h) {
            const float v = fmaxf(hc[h], 0.f);
            #pragma unroll
            for (int j = 0; j < 4; ++j) {
                const float4 w = LDC4(cw.Wr2o, (base + h) * ED + 4 * j);
                ro[4*j+0] = fmaf(v, w.x, ro[4*j+0]);
                ro[4*j+1] = fmaf(v, w.y, ro[4*j+1]);
                ro[4*j+2] = fmaf(v, w.z, ro[4*j+2]);
                ro[4*j+3] = fmaf(v, w.w, ro[4*j+3]);
            }
        }
    }

    // ======================= psi head =======================
    const float4 gv = xp[(size_t)20 * BMAX + t];
    const float gs[4] = { gv.x, gv.y, gv.z, gv.w };
    float a0 = cw.bpsi2[0], a1 = cw.bpsi2[1];
    #pragma unroll 1
    for (int c = 0; c < 4; ++c) {
        const int base = c * 16;
        float hc[16];
        #pragma unroll
        for (int q = 0; q < 4; ++q) {
            const float4 b = LDC4(cw.bpsi1, base + 4 * q);
            hc[4*q+0] = b.x; hc[4*q+1] = b.y; hc[4*q+2] = b.z; hc[4*q+3] = b.w;
        }
        #pragma unroll
        for (int i = 0; i < ED; ++i) {
            const float v = rn[i];
            #pragma unroll
            for (int j = 0; j < 4; ++j) {
                const float4 w = LDC4(cw.Wpsi1, i * HP + base + 4 * j);
                hc[4*j+0] = fmaf(v, w.x, hc[4*j+0]);
                hc[4*j+1] = fmaf(v, w.y, hc[4*j+1]);
                hc[4*j+2] = fmaf(v, w.z, hc[4*j+2]);
                hc[4*j+3] = fmaf(v, w.w, hc[4*j+3]);
            }
        }
        #pragma unroll
        for (int i = 0; i < ED; ++i) {
            const float v = ro[i];
            #pragma unroll
            for (int j = 0; j < 4; ++j) {
                const float4 w = LDC4(cw.Wpsi1, (ED + i) * HP + base + 4 * j);
                hc[4*j+0] = fmaf(v, w.x, hc[4*j+0]);
                hc[4*j+1] = fmaf(v, w.y, hc[4*j+1]);
                hc[4*j+2] = fmaf(v, w.z, hc[4*j+2]);
                hc[4*j+3] = fmaf(v, w.w, hc[4*j+3]);
            }
        }
        #pragma unroll
        for (int k = 0; k < 4; ++k) {
            const float v = gs[k];
            #pragma unroll
            for (int j = 0; j < 4; ++j) {
                const float4 w = LDC4(cw.Wpsi1, (2 * ED + k) * HP + base + 4 * j);
                hc[4*j+0] = fmaf(v, w.x, hc[4*j+0]);
                hc[4*j+1] = fmaf(v, w.y, hc[4*j+1]);
                hc[4*j+2] = fmaf(v, w.z, hc[4*j+2]);
                hc[4*j+3] = fmaf(v, w.w, hc[4*j+3]);
            }
        }
        #pragma unroll
        for (int h = 0; h < 16; h += 2) {
            const float v0 = fmaxf(hc[h], 0.f);
            const float v1 = fmaxf(hc[h + 1], 0.f);
            const float4 w = LDC4(cw.Wpsi2, 2 * (base + h));
            a0 = fmaf(v0, w.x, a0); a1 = fmaf(v0, w.y, a1);
            a0 = fmaf(v1, w.z, a0); a1 = fmaf(v1, w.w, a1);
        }
    }

    a0 = fmaf(2.0f, tanhf(a0), bx);
    a1 = fmaf(2.0f, tanhf(a1), by);

    const float inv = fmaxf(fmaxf(fabsf(a0), fabsf(a1)) * 0.5f, 1.0f);
    const float r   = __fdividef(1.0f, inv);
    float2 res;
    res.x = a0 * r;
    res.y = a1 * r;
    reinterpret_cast<float2*>(out)[t] = res;
}

extern "C" void kernel_launch(void* const* d_in, const int* in_sizes, int n_in,
                              void* d_out, int out_size) {
    const float* x = (const float*)d_in[0];
    float* out = (float*)d_out;
    const int nb = in_sizes[0] / XC;

    WPtrs w;
    for (int i = 0; i < 20; ++i) w.p[i] = (const float*)d_in[i + 1];

    const int nbBlocks = (nb + 31) / 32;
    prep_kernel<<<nbBlocks + 18, 256>>>(x, nb, nbBlocks, w);

    void* blobAddr = nullptr;
    cudaGetSymbolAddress(&blobAddr, g_wblob);
    cudaMemcpyToSymbolAsync(cw, blobAddr, sizeof(CW), 0, cudaMemcpyDeviceToDevice, 0);

    const int threads = 256;
    const int blocks = (nb + threads - 1) / threads;
    bnet_kernel<<<blocks, threads>>>(out, nb);
}